// round 11
// baseline (speedup 1.0000x reference)
#include <cuda_runtime.h>
#include <cuda_fp16.h>
#include <cstdint>

// ---------------- problem constants ----------------
#define N_IMG   32
#define C_IN    256
#define HW      64
#define K_OUT   256
#define X_ELEMS (N_IMG * C_IN * HW * HW)          // 33554432
#define W_ELEMS (K_OUT * C_IN * 9)                // 589824
#define NWBLK   (W_ELEMS / 16)                    // 36864
#define NTILE   32
#define TILES_PER_IMG (NTILE * NTILE)             // 1024
#define NTILES_ALL (N_IMG * TILES_PER_IMG)        // 32768
#define DT_POS_STRIDE ((size_t)NTILES_ALL * C_IN) // 8388608
#define MT_POS_STRIDE ((size_t)K_OUT * NTILES_ALL)// 8388608

// ---------------- scratch ----------------
__device__ uint8_t g_xq[X_ELEMS];                     // NHWC fp8 (exact quantized)
__device__ uint8_t g_wq2[9 * K_OUT * C_IN];           // [rs][k][c] fp8 (exact)
__device__ __half  g_gt[16 * K_OUT * C_IN];           // winograd weights fp16
__device__ __half  g_dt[16ull * DT_POS_STRIDE];       // winograd data fp16
__device__ __half  g_mt[16ull * MT_POS_STRIDE];       // winograd product fp16

// ---------------- fp8 helpers ----------------
__device__ __forceinline__ uint16_t pack_e4m3_x2(float lo, float hi) {
    uint16_t r;
    asm volatile("cvt.rn.satfinite.e4m3x2.f32 %0, %1, %2;" : "=h"(r) : "f"(hi), "f"(lo));
    return r;
}
__device__ __forceinline__ uint8_t f32_to_e4m3(float v) {
    uint16_t r;
    asm volatile("cvt.rn.satfinite.e4m3x2.f32 %0, %1, %2;" : "=h"(r) : "f"(0.0f), "f"(v));
    return (uint8_t)(r & 0xFF);
}
__device__ __forceinline__ float e4m3_to_f32(uint8_t b) {
    uint16_t s = b;
    uint32_t h2;
    asm("cvt.rn.f16x2.e4m3x2 %0, %1;" : "=r"(h2) : "h"(s));
    __half lo = __ushort_as_half((uint16_t)(h2 & 0xFFFF));
    return __half2float(lo);
}

// ---------------- fake-quant core (exact pow2 scale + RTN E2M1) ----------------
__device__ __forceinline__ void quant16f(const float* __restrict__ v,
                                         float* __restrict__ q) {
    float amax = 0.0f;
#pragma unroll
    for (int i = 0; i < 16; ++i) amax = fmaxf(amax, fabsf(v[i]));
    float scale = 1.0f;
    if (amax > 0.0f) {
        float y = fmaxf(amax, 1e-30f) / 6.0f;
        int e;
        float m = frexpf(y, &e);
        scale = ldexpf(1.0f, (m == 0.5f) ? (e - 1) : e);
    }
    float inv = 1.0f / scale;
#pragma unroll
    for (int i = 0; i < 16; ++i) {
        float u = v[i] * inv;
        float a = fabsf(u);
        float g;
        if      (a < 0.25f) g = 0.0f;
        else if (a < 0.75f) g = 0.5f;
        else if (a < 1.25f) g = 1.0f;
        else if (a < 1.75f) g = 1.5f;
        else if (a < 2.5f)  g = 2.0f;
        else if (a < 3.5f)  g = 3.0f;
        else if (a < 5.0f)  g = 4.0f;
        else                g = 6.0f;
        q[i] = copysignf(g, u) * scale;     // exact in e4m3
    }
}

// ---------------- x quant -> NHWC fp8 (proven, ~51us) ----------------
__global__ void __launch_bounds__(256)
quant_x_nhwc(const float* __restrict__ x, uint8_t* __restrict__ xq) {
    __shared__ uint16_t buf[64][136];
    const int n = blockIdx.x;
    const int h = blockIdx.y;
    const int t = threadIdx.x;
    const int cp  = t & 127;
    const int wb0 = t >> 7;

#pragma unroll
    for (int wbi = 0; wbi < 2; ++wbi) {
        int wb = wb0 + wbi * 2;
        const float* base = x + (((size_t)n * C_IN + 2 * cp) * HW + h) * HW + wb * 16;
        const float4* p0 = reinterpret_cast<const float4*>(base);
        const float4* p1 = reinterpret_cast<const float4*>(base + (size_t)HW * HW);
        float v0[16], v1[16];
#pragma unroll
        for (int i = 0; i < 4; ++i) {
            float4 a = p0[i];
            v0[i * 4 + 0] = a.x; v0[i * 4 + 1] = a.y; v0[i * 4 + 2] = a.z; v0[i * 4 + 3] = a.w;
            float4 b = p1[i];
            v1[i * 4 + 0] = b.x; v1[i * 4 + 1] = b.y; v1[i * 4 + 2] = b.z; v1[i * 4 + 3] = b.w;
        }
        float q0[16], q1[16];
        quant16f(v0, q0);
        quant16f(v1, q1);
#pragma unroll
        for (int j = 0; j < 16; ++j)
            buf[wb * 16 + j][cp] = pack_e4m3_x2(q0[j], q1[j]);
    }
    __syncthreads();

    uint8_t* orow = xq + (((size_t)n * HW + h) * HW) * C_IN;
#pragma unroll
    for (int i = 0; i < 4; ++i) {
        int idx = t + 256 * i;
        int p   = idx >> 4;
        int qd  = idx & 15;
        uint4 val = *reinterpret_cast<const uint4*>(&buf[p][qd * 8]);
        *reinterpret_cast<uint4*>(orow + (size_t)p * C_IN + qd * 16) = val;
    }
}

// ---------------- w quant + repack -> [rs][k][c] fp8 (proven) ----------------
__global__ void quant_w_repack(const float* __restrict__ w,
                               uint8_t* __restrict__ wq2) {
    int b = blockIdx.x * blockDim.x + threadIdx.x;
    if (b >= NWBLK) return;
    const float4* src = reinterpret_cast<const float4*>(w) + (size_t)b * 4;
    float4 t0 = src[0], t1 = src[1], t2 = src[2], t3 = src[3];
    float v[16] = {t0.x, t0.y, t0.z, t0.w, t1.x, t1.y, t1.z, t1.w,
                   t2.x, t2.y, t2.z, t2.w, t3.x, t3.y, t3.z, t3.w};
    float q[16];
    quant16f(v, q);
#pragma unroll
    for (int i = 0; i < 16; ++i) {
        int f  = b * 16 + i;
        int k  = f / 2304;
        int r2 = f - k * 2304;
        int c  = r2 / 9;
        int rs = r2 - c * 9;
        wq2[((size_t)rs * K_OUT + k) * C_IN + c] = f32_to_e4m3(q[i]);
    }
}

// ---------------- winograd weight transform (proven) ----------------
__global__ void __launch_bounds__(256)
wg_transform(const uint8_t* __restrict__ wq2, __half* __restrict__ gt) {
    int k = blockIdx.x;
    int c = threadIdx.x;
    float w9[9];
#pragma unroll
    for (int rs = 0; rs < 9; ++rs)
        w9[rs] = e4m3_to_f32(wq2[((size_t)rs * K_OUT + k) * C_IN + c]);
    float a[4][3];
#pragma unroll
    for (int j = 0; j < 3; ++j) {
        float w0 = w9[0 * 3 + j], w1 = w9[1 * 3 + j], w2 = w9[2 * 3 + j];
        a[0][j] = w0;
        a[1][j] = 0.5f * (w0 + w1 + w2);
        a[2][j] = 0.5f * (w0 - w1 + w2);
        a[3][j] = w2;
    }
#pragma unroll
    for (int i = 0; i < 4; ++i) {
        float u0 = a[i][0], u1 = a[i][1], u2 = a[i][2];
        float u[4] = {u0, 0.5f * (u0 + u1 + u2), 0.5f * (u0 - u1 + u2), u2};
#pragma unroll
        for (int j = 0; j < 4; ++j)
            gt[((size_t)(i * 4 + j) * K_OUT + k) * C_IN + c] = __float2half(u[j]);
    }
}

// ---------------- cp.async helpers ----------------
__device__ __forceinline__ void cp_async16(void* dst, const void* src, bool pred) {
    uint32_t d = (uint32_t)__cvta_generic_to_shared(dst);
    int sz = pred ? 16 : 0;
    asm volatile("cp.async.cg.shared.global [%0], [%1], 16, %2;\n"
                 :: "r"(d), "l"(src), "r"(sz));
}
__device__ __forceinline__ void cp_commit() {
    asm volatile("cp.async.commit_group;\n");
}
template <int N>
__device__ __forceinline__ void cp_wait() {
    asm volatile("cp.async.wait_group %0;\n" :: "n"(N));
}

// ---------------- winograd data transform (proven, 46us) ----------------
__global__ void __launch_bounds__(256)
dt_transform(const uint8_t* __restrict__ xq, __half* __restrict__ dt) {
    extern __shared__ uint8_t sx[];
    const int n  = blockIdx.x;
    const int th = blockIdx.y;
    const int t  = threadIdx.x;

#pragma unroll
    for (int i = 0; i < 16; ++i) {
        int idx = t + 256 * i;
        int h1  = idx >> 10;
        int rem = idx & 1023;
        int w   = rem >> 4;
        int cq  = rem & 15;
        int gh  = th * 2 - 1 + h1;
        bool ok = (unsigned)gh < (unsigned)HW;
        cp_async16(sx + ((size_t)h1 * 64 + w) * 256 + cq * 16,
                   xq + (((size_t)n * HW + (ok ? gh : 0)) * HW + w) * C_IN + cq * 16, ok);
    }
    cp_commit();
    cp_wait<0>();
    __syncthreads();

    const int cp  = t & 127;
    const int twh = t >> 7;
    const __half2 zero = __floats2half2_rn(0.f, 0.f);

#pragma unroll 1
    for (int j = 0; j < 16; ++j) {
        int tw = j * 2 + twh;
        __half2 d[4][4];
#pragma unroll
        for (int wi = 0; wi < 4; ++wi) {
            int w = 2 * tw - 1 + wi;
            bool ok = (unsigned)w < (unsigned)HW;
#pragma unroll
            for (int h1 = 0; h1 < 4; ++h1) {
                if (ok) {
                    uint16_t u = *reinterpret_cast<const uint16_t*>(
                        sx + ((size_t)h1 * 64 + w) * 256 + 2 * cp);
                    uint32_t h2;
                    asm("cvt.rn.f16x2.e4m3x2 %0, %1;" : "=r"(h2) : "h"(u));
                    d[h1][wi] = *reinterpret_cast<__half2*>(&h2);
                } else {
                    d[h1][wi] = zero;
                }
            }
        }
        __half2 e[4][4];
#pragma unroll
        for (int h1 = 0; h1 < 4; ++h1) {
            e[h1][0] = __hsub2(d[h1][0], d[h1][2]);
            e[h1][1] = __hadd2(d[h1][1], d[h1][2]);
            e[h1][2] = __hsub2(d[h1][2], d[h1][1]);
            e[h1][3] = __hsub2(d[h1][1], d[h1][3]);
        }
        size_t tb = ((size_t)n * TILES_PER_IMG + th * NTILE + tw) * C_IN + 2 * cp;
#pragma unroll
        for (int jj = 0; jj < 4; ++jj) {
            __half2 D[4];
            D[0] = __hsub2(e[0][jj], e[2][jj]);
            D[1] = __hadd2(e[1][jj], e[2][jj]);
            D[2] = __hsub2(e[2][jj], e[1][jj]);
            D[3] = __hsub2(e[1][jj], e[3][jj]);
#pragma unroll
            for (int ii = 0; ii < 4; ++ii)
                *reinterpret_cast<uint32_t*>(&dt[(size_t)(ii * 4 + jj) * DT_POS_STRIDE + tb]) =
                    *reinterpret_cast<uint32_t*>(&D[ii]);
        }
    }
}

// ---------------- ldsm / mma ----------------
__device__ __forceinline__ void ldsm_x4(uint32_t addr, uint32_t& r0, uint32_t& r1,
                                        uint32_t& r2, uint32_t& r3) {
    asm volatile("ldmatrix.sync.aligned.m8n8.x4.shared.b16 {%0,%1,%2,%3}, [%4];"
                 : "=r"(r0), "=r"(r1), "=r"(r2), "=r"(r3) : "r"(addr));
}
__device__ __forceinline__ void mma16816f16(float* d, const uint32_t* a,
                                            uint32_t b0, uint32_t b1) {
    asm volatile("mma.sync.aligned.m16n8k16.row.col.f32.f16.f16.f32 "
                 "{%0,%1,%2,%3}, {%4,%5,%6,%7}, {%8,%9}, {%0,%1,%2,%3};"
                 : "+f"(d[0]), "+f"(d[1]), "+f"(d[2]), "+f"(d[3])
                 : "r"(a[0]), "r"(a[1]), "r"(a[2]), "r"(a[3]), "r"(b0), "r"(b1));
}

// ---------------- batched winograd GEMM: M[pos,k,t] = gt[pos,k,:].dt[pos,t,:] --
// CTA: 128k x 256t, one pos. 512 thr, 16 warps (2 wk x 8 wt), warp 64k x 32t.
// smem: 384 rows (128 A-k + 256 B-t) x 48B, double buffered.
#define GROWS   384
#define GSTAGE  (GROWS * 48)        // 18432
#define GSMEM   (2 * GSTAGE)        // 36864

__device__ __forceinline__ void gemm_stage(char* base,
                                           const __half* __restrict__ gt,
                                           const __half* __restrict__ dt,
                                           int pos, int k0, int t0, int cc, int t) {
#pragma unroll
    for (int i = 0; i < 2; ++i) {
        int u = t + 512 * i;                  // 0..1023, need 768
        if (u < 768) {
            int row  = u >> 1;
            int half = u & 1;
            const void* src;
            if (row < 128)
                src = gt + ((size_t)pos * K_OUT + k0 + row) * C_IN + cc + half * 8;
            else
                src = dt + (size_t)pos * DT_POS_STRIDE
                         + (size_t)(t0 + row - 128) * C_IN + cc + half * 8;
            cp_async16(base + row * 48 + half * 16, src, true);
        }
    }
}

__global__ void __launch_bounds__(512, 1)
wino_gemm(const __half* __restrict__ gt, const __half* __restrict__ dt,
          __half* __restrict__ mt) {
    extern __shared__ char smem[];
    const int kt  = blockIdx.x;               // 0..1
    const int tt  = blockIdx.y;               // 0..127
    const int pos = blockIdx.z;               // 0..15
    const int k0 = kt * 128;
    const int t0 = tt * 256;

    const int t    = threadIdx.x;
    const int lane = t & 31;
    const int warp = t >> 5;
    const int wk   = warp & 1;                // 64-k half
    const int wt   = warp >> 1;               // 32-t group

    float acc[4][4][4];
#pragma unroll
    for (int i = 0; i < 4; ++i)
#pragma unroll
        for (int j = 0; j < 4; ++j)
#pragma unroll
            for (int v = 0; v < 4; ++v) acc[i][j][v] = 0.0f;

    gemm_stage(smem, gt, dt, pos, k0, t0, 0, t);
    cp_commit();

    const uint32_t su = (uint32_t)__cvta_generic_to_shared(smem);
    const int a_off = (lane & 15) * 48 + (lane >> 4) * 16;
    const int b_off = ((lane & 7) + (lane >> 4) * 8) * 48 + ((lane >> 3) & 1) * 16;

#pragma unroll 1
    for (int it = 0; it < 16; ++it) {
        const int cur = it & 1;
        if (it + 1 < 16) {
            gemm_stage(smem + (cur ^ 1) * GSTAGE, gt, dt, pos, k0, t0,
                       (it + 1) * 16, t);
            cp_commit();
            cp_wait<1>();
        } else {
            cp_wait<0>();
        }
        __syncthreads();

        const uint32_t sA = su + cur * GSTAGE;
        const uint32_t sB = sA + 128 * 48;

        uint32_t a[4][4];
#pragma unroll
        for (int i = 0; i < 4; ++i)
            ldsm_x4(sA + (wk * 64 + i * 16) * 48 + a_off,
                    a[i][0], a[i][1], a[i][2], a[i][3]);
#pragma unroll
        for (int j = 0; j < 2; ++j) {
            uint32_t b[4];
            ldsm_x4(sB + (wt * 32 + j * 16) * 48 + b_off, b[0], b[1], b[2], b[3]);
#pragma unroll
            for (int i = 0; i < 4; ++i) {
                mma16816f16(acc[i][2 * j],     a[i], b[0], b[1]);
                mma16816f16(acc[i][2 * j + 1], a[i], b[2], b[3]);
            }
        }
        __syncthreads();
    }

    // epilogue: fp16 M, layout [pos][k][gtile]
    const int g  = lane >> 2;
    const int tc = lane & 3;
    __half* mbase = mt + (size_t)pos * MT_POS_STRIDE;
#pragma unroll
    for (int i = 0; i < 4; ++i) {
        const int krow = k0 + wk * 64 + i * 16 + g;
#pragma unroll
        for (int j = 0; j < 4; ++j) {
            const int tcol = t0 + wt * 32 + j * 8 + 2 * tc;
            __half2 v0 = __floats2half2_rn(acc[i][j][0], acc[i][j][1]);
            __half2 v1 = __floats2half2_rn(acc[i][j][2], acc[i][j][3]);
            *reinterpret_cast<__half2*>(&mbase[(size_t)krow * NTILES_ALL + tcol]) = v0;
            *reinterpret_cast<__half2*>(&mbase[(size_t)(krow + 8) * NTILES_ALL + tcol]) = v1;
        }
    }
}

// ---------------- inverse transform: y = A^T M A (memory-bound) ----------------
__global__ void __launch_bounds__(256)
wino_inverse(const __half* __restrict__ mt, float* __restrict__ out) {
    const size_t idx = (size_t)blockIdx.x * 256 + threadIdx.x;   // 8.4M
    const int gtile = (int)(idx & (NTILES_ALL - 1));
    const int k     = (int)(idx >> 15);

    float m[16];
#pragma unroll
    for (int p = 0; p < 16; ++p)
        m[p] = __half2float(__ldg(&mt[(size_t)p * MT_POS_STRIDE
                                      + (size_t)k * NTILES_ALL + gtile]));

    float z0[4], z1[4];
#pragma unroll
    for (int i = 0; i < 4; ++i) {
        z0[i] = m[i * 4 + 0] + m[i * 4 + 1] + m[i * 4 + 2];
        z1[i] = m[i * 4 + 1] - m[i * 4 + 2] - m[i * 4 + 3];
    }
    float y00 = z0[0] + z0[1] + z0[2];
    float y01 = z1[0] + z1[1] + z1[2];
    float y10 = z0[1] - z0[2] - z0[3];
    float y11 = z1[1] - z1[2] - z1[3];

    const int n  = gtile >> 10;
    const int th = (gtile >> 5) & 31;
    const int tw = gtile & 31;
    size_t ob = (((size_t)n * K_OUT + k) * HW + 2 * th) * HW + 2 * tw;
    *reinterpret_cast<float2*>(out + ob)      = make_float2(y00, y01);
    *reinterpret_cast<float2*>(out + ob + HW) = make_float2(y10, y11);
}

// ---------------- launch ----------------
extern "C" void kernel_launch(void* const* d_in, const int* in_sizes, int n_in,
                              void* d_out, int out_size) {
    const float* x = (const float*)d_in[0];
    const float* w = (const float*)d_in[1];
    if (in_sizes[0] != X_ELEMS) {
        x = (const float*)d_in[1];
        w = (const float*)d_in[0];
    }

    void *xq_p, *wq_p, *gt_p, *dt_p, *mt_p;
    cudaGetSymbolAddress(&xq_p, g_xq);
    cudaGetSymbolAddress(&wq_p, g_wq2);
    cudaGetSymbolAddress(&gt_p, g_gt);
    cudaGetSymbolAddress(&dt_p, g_dt);
    cudaGetSymbolAddress(&mt_p, g_mt);
    uint8_t* xq  = (uint8_t*)xq_p;
    uint8_t* wq2 = (uint8_t*)wq_p;
    __half*  gt  = (__half*)gt_p;
    __half*  dt  = (__half*)dt_p;
    __half*  mt  = (__half*)mt_p;

    cudaFuncSetAttribute(dt_transform,
                         cudaFuncAttributeMaxDynamicSharedMemorySize, 65536);
    cudaFuncSetAttribute(wino_gemm,
                         cudaFuncAttributeMaxDynamicSharedMemorySize, GSMEM);

    quant_x_nhwc<<<dim3(N_IMG, HW), 256>>>(x, xq);
    quant_w_repack<<<(NWBLK + 255) / 256, 256>>>(w, wq2);
    wg_transform<<<K_OUT, C_IN>>>(wq2, gt);
    dt_transform<<<dim3(N_IMG, NTILE), 256, 65536>>>(xq, dt);
    wino_gemm<<<dim3(2, 128, 16), 512, GSMEM>>>(gt, dt, mt);
    wino_inverse<<<NTILES_ALL, 256>>>(mt, (float*)d_out);
}

// round 12
// speedup vs baseline: 1.0119x; 1.0119x over previous
#include <cuda_runtime.h>
#include <cuda_fp16.h>
#include <cstdint>

// ---------------- problem constants ----------------
#define N_IMG   32
#define C_IN    256
#define HW      64
#define K_OUT   256
#define X_ELEMS (N_IMG * C_IN * HW * HW)          // 33554432
#define W_ELEMS (K_OUT * C_IN * 9)                // 589824
#define NWBLK   (W_ELEMS / 16)                    // 36864
#define NTILE   32
#define TILES_PER_IMG (NTILE * NTILE)             // 1024
#define NTILES_ALL (N_IMG * TILES_PER_IMG)        // 32768
#define DT_POS_STRIDE ((size_t)NTILES_ALL * C_IN) // 8388608
#define MT_POS_STRIDE ((size_t)K_OUT * NTILES_ALL)// 8388608

// ---------------- scratch ----------------
__device__ uint8_t g_xq[X_ELEMS];                     // NHWC fp8 (exact quantized)
__device__ uint8_t g_wq2[9 * K_OUT * C_IN];           // [rs][k][c] fp8 (exact)
__device__ __half  g_gt[16 * K_OUT * C_IN];           // winograd weights fp16
__device__ __half  g_dt[16ull * DT_POS_STRIDE];       // winograd data fp16
__device__ __half  g_mt[16ull * MT_POS_STRIDE];       // winograd product fp16

// ---------------- fp8 helpers ----------------
__device__ __forceinline__ uint16_t pack_e4m3_x2(float lo, float hi) {
    uint16_t r;
    asm volatile("cvt.rn.satfinite.e4m3x2.f32 %0, %1, %2;" : "=h"(r) : "f"(hi), "f"(lo));
    return r;
}
__device__ __forceinline__ uint8_t f32_to_e4m3(float v) {
    uint16_t r;
    asm volatile("cvt.rn.satfinite.e4m3x2.f32 %0, %1, %2;" : "=h"(r) : "f"(0.0f), "f"(v));
    return (uint8_t)(r & 0xFF);
}
__device__ __forceinline__ float e4m3_to_f32(uint8_t b) {
    uint16_t s = b;
    uint32_t h2;
    asm("cvt.rn.f16x2.e4m3x2 %0, %1;" : "=r"(h2) : "h"(s));
    __half lo = __ushort_as_half((uint16_t)(h2 & 0xFFFF));
    return __half2float(lo);
}

// ---------------- fake-quant core (exact pow2 scale + RTN E2M1) ----------------
__device__ __forceinline__ void quant16f(const float* __restrict__ v,
                                         float* __restrict__ q) {
    float amax = 0.0f;
#pragma unroll
    for (int i = 0; i < 16; ++i) amax = fmaxf(amax, fabsf(v[i]));
    float scale = 1.0f;
    if (amax > 0.0f) {
        float y = fmaxf(amax, 1e-30f) / 6.0f;
        int e;
        float m = frexpf(y, &e);
        scale = ldexpf(1.0f, (m == 0.5f) ? (e - 1) : e);
    }
    float inv = 1.0f / scale;
#pragma unroll
    for (int i = 0; i < 16; ++i) {
        float u = v[i] * inv;
        float a = fabsf(u);
        float g;
        if      (a < 0.25f) g = 0.0f;
        else if (a < 0.75f) g = 0.5f;
        else if (a < 1.25f) g = 1.0f;
        else if (a < 1.75f) g = 1.5f;
        else if (a < 2.5f)  g = 2.0f;
        else if (a < 3.5f)  g = 3.0f;
        else if (a < 5.0f)  g = 4.0f;
        else                g = 6.0f;
        q[i] = copysignf(g, u) * scale;     // exact in e4m3
    }
}

// ---------------- x quant -> NHWC fp8 (proven, ~51us) ----------------
__global__ void __launch_bounds__(256)
quant_x_nhwc(const float* __restrict__ x, uint8_t* __restrict__ xq) {
    __shared__ uint16_t buf[64][136];
    const int n = blockIdx.x;
    const int h = blockIdx.y;
    const int t = threadIdx.x;
    const int cp  = t & 127;
    const int wb0 = t >> 7;

#pragma unroll
    for (int wbi = 0; wbi < 2; ++wbi) {
        int wb = wb0 + wbi * 2;
        const float* base = x + (((size_t)n * C_IN + 2 * cp) * HW + h) * HW + wb * 16;
        const float4* p0 = reinterpret_cast<const float4*>(base);
        const float4* p1 = reinterpret_cast<const float4*>(base + (size_t)HW * HW);
        float v0[16], v1[16];
#pragma unroll
        for (int i = 0; i < 4; ++i) {
            float4 a = p0[i];
            v0[i * 4 + 0] = a.x; v0[i * 4 + 1] = a.y; v0[i * 4 + 2] = a.z; v0[i * 4 + 3] = a.w;
            float4 b = p1[i];
            v1[i * 4 + 0] = b.x; v1[i * 4 + 1] = b.y; v1[i * 4 + 2] = b.z; v1[i * 4 + 3] = b.w;
        }
        float q0[16], q1[16];
        quant16f(v0, q0);
        quant16f(v1, q1);
#pragma unroll
        for (int j = 0; j < 16; ++j)
            buf[wb * 16 + j][cp] = pack_e4m3_x2(q0[j], q1[j]);
    }
    __syncthreads();

    uint8_t* orow = xq + (((size_t)n * HW + h) * HW) * C_IN;
#pragma unroll
    for (int i = 0; i < 4; ++i) {
        int idx = t + 256 * i;
        int p   = idx >> 4;
        int qd  = idx & 15;
        uint4 val = *reinterpret_cast<const uint4*>(&buf[p][qd * 8]);
        *reinterpret_cast<uint4*>(orow + (size_t)p * C_IN + qd * 16) = val;
    }
}

// ---------------- w quant + repack -> [rs][k][c] fp8 (proven) ----------------
__global__ void quant_w_repack(const float* __restrict__ w,
                               uint8_t* __restrict__ wq2) {
    int b = blockIdx.x * blockDim.x + threadIdx.x;
    if (b >= NWBLK) return;
    const float4* src = reinterpret_cast<const float4*>(w) + (size_t)b * 4;
    float4 t0 = src[0], t1 = src[1], t2 = src[2], t3 = src[3];
    float v[16] = {t0.x, t0.y, t0.z, t0.w, t1.x, t1.y, t1.z, t1.w,
                   t2.x, t2.y, t2.z, t2.w, t3.x, t3.y, t3.z, t3.w};
    float q[16];
    quant16f(v, q);
#pragma unroll
    for (int i = 0; i < 16; ++i) {
        int f  = b * 16 + i;
        int k  = f / 2304;
        int r2 = f - k * 2304;
        int c  = r2 / 9;
        int rs = r2 - c * 9;
        wq2[((size_t)rs * K_OUT + k) * C_IN + c] = f32_to_e4m3(q[i]);
    }
}

// ---------------- winograd weight transform (proven) ----------------
__global__ void __launch_bounds__(256)
wg_transform(const uint8_t* __restrict__ wq2, __half* __restrict__ gt) {
    int k = blockIdx.x;
    int c = threadIdx.x;
    float w9[9];
#pragma unroll
    for (int rs = 0; rs < 9; ++rs)
        w9[rs] = e4m3_to_f32(wq2[((size_t)rs * K_OUT + k) * C_IN + c]);
    float a[4][3];
#pragma unroll
    for (int j = 0; j < 3; ++j) {
        float w0 = w9[0 * 3 + j], w1 = w9[1 * 3 + j], w2 = w9[2 * 3 + j];
        a[0][j] = w0;
        a[1][j] = 0.5f * (w0 + w1 + w2);
        a[2][j] = 0.5f * (w0 - w1 + w2);
        a[3][j] = w2;
    }
#pragma unroll
    for (int i = 0; i < 4; ++i) {
        float u0 = a[i][0], u1 = a[i][1], u2 = a[i][2];
        float u[4] = {u0, 0.5f * (u0 + u1 + u2), 0.5f * (u0 - u1 + u2), u2};
#pragma unroll
        for (int j = 0; j < 4; ++j)
            gt[((size_t)(i * 4 + j) * K_OUT + k) * C_IN + c] = __float2half(u[j]);
    }
}

// ---------------- cp.async helpers ----------------
__device__ __forceinline__ void cp_async16(void* dst, const void* src, bool pred) {
    uint32_t d = (uint32_t)__cvta_generic_to_shared(dst);
    int sz = pred ? 16 : 0;
    asm volatile("cp.async.cg.shared.global [%0], [%1], 16, %2;\n"
                 :: "r"(d), "l"(src), "r"(sz));
}
__device__ __forceinline__ void cp_commit() {
    asm volatile("cp.async.commit_group;\n");
}
template <int N>
__device__ __forceinline__ void cp_wait() {
    asm volatile("cp.async.wait_group %0;\n" :: "n"(N));
}

// ---------------- winograd data transform (proven, 46us) ----------------
__global__ void __launch_bounds__(256)
dt_transform(const uint8_t* __restrict__ xq, __half* __restrict__ dt) {
    extern __shared__ uint8_t sx[];
    const int n  = blockIdx.x;
    const int th = blockIdx.y;
    const int t  = threadIdx.x;

#pragma unroll
    for (int i = 0; i < 16; ++i) {
        int idx = t + 256 * i;
        int h1  = idx >> 10;
        int rem = idx & 1023;
        int w   = rem >> 4;
        int cq  = rem & 15;
        int gh  = th * 2 - 1 + h1;
        bool ok = (unsigned)gh < (unsigned)HW;
        cp_async16(sx + ((size_t)h1 * 64 + w) * 256 + cq * 16,
                   xq + (((size_t)n * HW + (ok ? gh : 0)) * HW + w) * C_IN + cq * 16, ok);
    }
    cp_commit();
    cp_wait<0>();
    __syncthreads();

    const int cp  = t & 127;
    const int twh = t >> 7;
    const __half2 zero = __floats2half2_rn(0.f, 0.f);

#pragma unroll 1
    for (int j = 0; j < 16; ++j) {
        int tw = j * 2 + twh;
        __half2 d[4][4];
#pragma unroll
        for (int wi = 0; wi < 4; ++wi) {
            int w = 2 * tw - 1 + wi;
            bool ok = (unsigned)w < (unsigned)HW;
#pragma unroll
            for (int h1 = 0; h1 < 4; ++h1) {
                if (ok) {
                    uint16_t u = *reinterpret_cast<const uint16_t*>(
                        sx + ((size_t)h1 * 64 + w) * 256 + 2 * cp);
                    uint32_t h2;
                    asm("cvt.rn.f16x2.e4m3x2 %0, %1;" : "=r"(h2) : "h"(u));
                    d[h1][wi] = *reinterpret_cast<__half2*>(&h2);
                } else {
                    d[h1][wi] = zero;
                }
            }
        }
        __half2 e[4][4];
#pragma unroll
        for (int h1 = 0; h1 < 4; ++h1) {
            e[h1][0] = __hsub2(d[h1][0], d[h1][2]);
            e[h1][1] = __hadd2(d[h1][1], d[h1][2]);
            e[h1][2] = __hsub2(d[h1][2], d[h1][1]);
            e[h1][3] = __hsub2(d[h1][1], d[h1][3]);
        }
        size_t tb = ((size_t)n * TILES_PER_IMG + th * NTILE + tw) * C_IN + 2 * cp;
#pragma unroll
        for (int jj = 0; jj < 4; ++jj) {
            __half2 D[4];
            D[0] = __hsub2(e[0][jj], e[2][jj]);
            D[1] = __hadd2(e[1][jj], e[2][jj]);
            D[2] = __hsub2(e[2][jj], e[1][jj]);
            D[3] = __hsub2(e[1][jj], e[3][jj]);
#pragma unroll
            for (int ii = 0; ii < 4; ++ii)
                *reinterpret_cast<uint32_t*>(&dt[(size_t)(ii * 4 + jj) * DT_POS_STRIDE + tb]) =
                    *reinterpret_cast<uint32_t*>(&D[ii]);
        }
    }
}

// ---------------- ldsm / mma ----------------
__device__ __forceinline__ void ldsm_x4(uint32_t addr, uint32_t& r0, uint32_t& r1,
                                        uint32_t& r2, uint32_t& r3) {
    asm volatile("ldmatrix.sync.aligned.m8n8.x4.shared.b16 {%0,%1,%2,%3}, [%4];"
                 : "=r"(r0), "=r"(r1), "=r"(r2), "=r"(r3) : "r"(addr));
}
__device__ __forceinline__ void mma16816f16(float* d, const uint32_t* a,
                                            uint32_t b0, uint32_t b1) {
    asm volatile("mma.sync.aligned.m16n8k16.row.col.f32.f16.f16.f32 "
                 "{%0,%1,%2,%3}, {%4,%5,%6,%7}, {%8,%9}, {%0,%1,%2,%3};"
                 : "+f"(d[0]), "+f"(d[1]), "+f"(d[2]), "+f"(d[3])
                 : "r"(a[0]), "r"(a[1]), "r"(a[2]), "r"(a[3]), "r"(b0), "r"(b1));
}

// ---------------- batched winograd GEMM v3 ----------------
// CTA: 256k x 128t, one pos. 256 thr, 8 warps (4 wk x 2 wt), warp 64k x 64t.
// MMA:LDSM = 32:8 per warp-chunk (3:1 cyc, MMA-bound). dt read ONCE per pos.
// smem: 384 rows (256 A-k + 128 B-t) x 48B, double buffered.
#define GROWS   384
#define GSTAGE  (GROWS * 48)        // 18432
#define GSMEM   (2 * GSTAGE)        // 36864

__device__ __forceinline__ void gemm_stage(char* base,
                                           const __half* __restrict__ gt,
                                           const __half* __restrict__ dt,
                                           int pos, int t0, int cc, int t) {
#pragma unroll
    for (int i = 0; i < 3; ++i) {
        int u    = t + 256 * i;               // 0..767
        int row  = u >> 1;
        int half = u & 1;
        const void* src;
        if (row < 256)
            src = gt + ((size_t)pos * K_OUT + row) * C_IN + cc + half * 8;
        else
            src = dt + (size_t)pos * DT_POS_STRIDE
                     + (size_t)(t0 + row - 256) * C_IN + cc + half * 8;
        cp_async16(base + row * 48 + half * 16, src, true);
    }
}

__global__ void __launch_bounds__(256, 1)
wino_gemm(const __half* __restrict__ gt, const __half* __restrict__ dt,
          __half* __restrict__ mt) {
    extern __shared__ char smem[];
    const int tt  = blockIdx.x;               // 0..255
    const int pos = blockIdx.y;               // 0..15
    const int t0 = tt * 128;

    const int t    = threadIdx.x;
    const int lane = t & 31;
    const int warp = t >> 5;
    const int wk   = warp & 3;                // 64-k group
    const int wt   = warp >> 2;               // 64-t group

    float acc[4][8][4];
#pragma unroll
    for (int i = 0; i < 4; ++i)
#pragma unroll
        for (int j = 0; j < 8; ++j)
#pragma unroll
            for (int v = 0; v < 4; ++v) acc[i][j][v] = 0.0f;

    gemm_stage(smem, gt, dt, pos, t0, 0, t);
    cp_commit();

    const uint32_t su = (uint32_t)__cvta_generic_to_shared(smem);
    const int a_off = (lane & 15) * 48 + (lane >> 4) * 16;
    const int b_off = ((lane & 7) + (lane >> 4) * 8) * 48 + ((lane >> 3) & 1) * 16;

#pragma unroll 1
    for (int it = 0; it < 16; ++it) {
        const int cur = it & 1;
        if (it + 1 < 16) {
            gemm_stage(smem + (cur ^ 1) * GSTAGE, gt, dt, pos, t0,
                       (it + 1) * 16, t);
            cp_commit();
            cp_wait<1>();
        } else {
            cp_wait<0>();
        }
        __syncthreads();

        const uint32_t sA = su + cur * GSTAGE;
        const uint32_t sB = sA + 256 * 48;

        uint32_t a[4][4];
#pragma unroll
        for (int i = 0; i < 4; ++i)
            ldsm_x4(sA + (wk * 64 + i * 16) * 48 + a_off,
                    a[i][0], a[i][1], a[i][2], a[i][3]);
#pragma unroll
        for (int j = 0; j < 4; ++j) {
            uint32_t b[4];
            ldsm_x4(sB + (wt * 64 + j * 16) * 48 + b_off, b[0], b[1], b[2], b[3]);
#pragma unroll
            for (int i = 0; i < 4; ++i) {
                mma16816f16(acc[i][2 * j],     a[i], b[0], b[1]);
                mma16816f16(acc[i][2 * j + 1], a[i], b[2], b[3]);
            }
        }
        __syncthreads();
    }

    // epilogue: fp16 M, layout [pos][k][gtile]
    const int g  = lane >> 2;
    const int tc = lane & 3;
    __half* mbase = mt + (size_t)pos * MT_POS_STRIDE;
#pragma unroll
    for (int i = 0; i < 4; ++i) {
        const int krow = wk * 64 + i * 16 + g;
#pragma unroll
        for (int j = 0; j < 8; ++j) {
            const int tcol = t0 + wt * 64 + j * 8 + 2 * tc;
            __half2 v0 = __floats2half2_rn(acc[i][j][0], acc[i][j][1]);
            __half2 v1 = __floats2half2_rn(acc[i][j][2], acc[i][j][3]);
            *reinterpret_cast<__half2*>(&mbase[(size_t)krow * NTILES_ALL + tcol]) = v0;
            *reinterpret_cast<__half2*>(&mbase[(size_t)(krow + 8) * NTILES_ALL + tcol]) = v1;
        }
    }
}

// ---------------- inverse transform: y = A^T M A (memory-bound) ----------------
__global__ void __launch_bounds__(256)
wino_inverse(const __half* __restrict__ mt, float* __restrict__ out) {
    const size_t idx = (size_t)blockIdx.x * 256 + threadIdx.x;   // 8.4M
    const int gtile = (int)(idx & (NTILES_ALL - 1));
    const int k     = (int)(idx >> 15);

    float m[16];
#pragma unroll
    for (int p = 0; p < 16; ++p)
        m[p] = __half2float(__ldg(&mt[(size_t)p * MT_POS_STRIDE
                                      + (size_t)k * NTILES_ALL + gtile]));

    float z0[4], z1[4];
#pragma unroll
    for (int i = 0; i < 4; ++i) {
        z0[i] = m[i * 4 + 0] + m[i * 4 + 1] + m[i * 4 + 2];
        z1[i] = m[i * 4 + 1] - m[i * 4 + 2] - m[i * 4 + 3];
    }
    float y00 = z0[0] + z0[1] + z0[2];
    float y01 = z1[0] + z1[1] + z1[2];
    float y10 = z0[1] - z0[2] - z0[3];
    float y11 = z1[1] - z1[2] - z1[3];

    const int n  = gtile >> 10;
    const int th = (gtile >> 5) & 31;
    const int tw = gtile & 31;
    size_t ob = (((size_t)n * K_OUT + k) * HW + 2 * th) * HW + 2 * tw;
    *reinterpret_cast<float2*>(out + ob)      = make_float2(y00, y01);
    *reinterpret_cast<float2*>(out + ob + HW) = make_float2(y10, y11);
}

// ---------------- launch ----------------
extern "C" void kernel_launch(void* const* d_in, const int* in_sizes, int n_in,
                              void* d_out, int out_size) {
    const float* x = (const float*)d_in[0];
    const float* w = (const float*)d_in[1];
    if (in_sizes[0] != X_ELEMS) {
        x = (const float*)d_in[1];
        w = (const float*)d_in[0];
    }

    void *xq_p, *wq_p, *gt_p, *dt_p, *mt_p;
    cudaGetSymbolAddress(&xq_p, g_xq);
    cudaGetSymbolAddress(&wq_p, g_wq2);
    cudaGetSymbolAddress(&gt_p, g_gt);
    cudaGetSymbolAddress(&dt_p, g_dt);
    cudaGetSymbolAddress(&mt_p, g_mt);
    uint8_t* xq  = (uint8_t*)xq_p;
    uint8_t* wq2 = (uint8_t*)wq_p;
    __half*  gt  = (__half*)gt_p;
    __half*  dt  = (__half*)dt_p;
    __half*  mt  = (__half*)mt_p;

    cudaFuncSetAttribute(dt_transform,
                         cudaFuncAttributeMaxDynamicSharedMemorySize, 65536);
    cudaFuncSetAttribute(wino_gemm,
                         cudaFuncAttributeMaxDynamicSharedMemorySize, GSMEM);

    quant_x_nhwc<<<dim3(N_IMG, HW), 256>>>(x, xq);
    quant_w_repack<<<(NWBLK + 255) / 256, 256>>>(w, wq2);
    wg_transform<<<K_OUT, C_IN>>>(wq2, gt);
    dt_transform<<<dim3(N_IMG, NTILE), 256, 65536>>>(xq, dt);
    wino_gemm<<<dim3(256, 16), 256, GSMEM>>>(gt, dt, mt);
    wino_inverse<<<NTILES_ALL, 256>>>(mt, (float*)d_out);
}

// round 13
// speedup vs baseline: 1.2205x; 1.2061x over previous
#include <cuda_runtime.h>
#include <cuda_fp16.h>
#include <cstdint>

// ---------------- problem constants ----------------
#define N_IMG   32
#define C_IN    256
#define HW      64
#define K_OUT   256
#define X_ELEMS (N_IMG * C_IN * HW * HW)          // 33554432
#define W_ELEMS (K_OUT * C_IN * 9)                // 589824
#define NWBLK   (W_ELEMS / 16)                    // 36864
#define NTILE   32
#define TILES_PER_IMG (NTILE * NTILE)             // 1024
#define NTILES_ALL (N_IMG * TILES_PER_IMG)        // 32768
#define DT_POS_STRIDE ((size_t)NTILES_ALL * C_IN) // 8388608
#define MT_POS_STRIDE ((size_t)K_OUT * NTILES_ALL)// 8388608

// ---------------- scratch ----------------
__device__ uint8_t g_xq[X_ELEMS];                     // NHWC fp8 (exact quantized)
__device__ uint8_t g_wq2[9 * K_OUT * C_IN];           // [rs][k][c] fp8 (exact)
__device__ __half  g_gt[16 * K_OUT * C_IN];           // winograd weights fp16
__device__ __half  g_dt[16ull * DT_POS_STRIDE];       // winograd data fp16
__device__ __half  g_mt[16ull * MT_POS_STRIDE];       // winograd product fp16

// ---------------- fp8 helpers ----------------
__device__ __forceinline__ uint16_t pack_e4m3_x2(float lo, float hi) {
    uint16_t r;
    asm volatile("cvt.rn.satfinite.e4m3x2.f32 %0, %1, %2;" : "=h"(r) : "f"(hi), "f"(lo));
    return r;
}
__device__ __forceinline__ uint8_t f32_to_e4m3(float v) {
    uint16_t r;
    asm volatile("cvt.rn.satfinite.e4m3x2.f32 %0, %1, %2;" : "=h"(r) : "f"(0.0f), "f"(v));
    return (uint8_t)(r & 0xFF);
}
__device__ __forceinline__ float e4m3_to_f32(uint8_t b) {
    uint16_t s = b;
    uint32_t h2;
    asm("cvt.rn.f16x2.e4m3x2 %0, %1;" : "=r"(h2) : "h"(s));
    __half lo = __ushort_as_half((uint16_t)(h2 & 0xFFFF));
    return __half2float(lo);
}

// ---------------- fake-quant core (exact pow2 scale + RTN E2M1) ----------------
__device__ __forceinline__ void quant16f(const float* __restrict__ v,
                                         float* __restrict__ q) {
    float amax = 0.0f;
#pragma unroll
    for (int i = 0; i < 16; ++i) amax = fmaxf(amax, fabsf(v[i]));
    float scale = 1.0f;
    if (amax > 0.0f) {
        float y = fmaxf(amax, 1e-30f) / 6.0f;
        int e;
        float m = frexpf(y, &e);
        scale = ldexpf(1.0f, (m == 0.5f) ? (e - 1) : e);
    }
    float inv = 1.0f / scale;
#pragma unroll
    for (int i = 0; i < 16; ++i) {
        float u = v[i] * inv;
        float a = fabsf(u);
        float g;
        if      (a < 0.25f) g = 0.0f;
        else if (a < 0.75f) g = 0.5f;
        else if (a < 1.25f) g = 1.0f;
        else if (a < 1.75f) g = 1.5f;
        else if (a < 2.5f)  g = 2.0f;
        else if (a < 3.5f)  g = 3.0f;
        else if (a < 5.0f)  g = 4.0f;
        else                g = 6.0f;
        q[i] = copysignf(g, u) * scale;     // exact in e4m3
    }
}

// ---------------- x quant -> NHWC fp8 (proven, ~51us) ----------------
__global__ void __launch_bounds__(256)
quant_x_nhwc(const float* __restrict__ x, uint8_t* __restrict__ xq) {
    __shared__ uint16_t buf[64][136];
    const int n = blockIdx.x;
    const int h = blockIdx.y;
    const int t = threadIdx.x;
    const int cp  = t & 127;
    const int wb0 = t >> 7;

#pragma unroll
    for (int wbi = 0; wbi < 2; ++wbi) {
        int wb = wb0 + wbi * 2;
        const float* base = x + (((size_t)n * C_IN + 2 * cp) * HW + h) * HW + wb * 16;
        const float4* p0 = reinterpret_cast<const float4*>(base);
        const float4* p1 = reinterpret_cast<const float4*>(base + (size_t)HW * HW);
        float v0[16], v1[16];
#pragma unroll
        for (int i = 0; i < 4; ++i) {
            float4 a = p0[i];
            v0[i * 4 + 0] = a.x; v0[i * 4 + 1] = a.y; v0[i * 4 + 2] = a.z; v0[i * 4 + 3] = a.w;
            float4 b = p1[i];
            v1[i * 4 + 0] = b.x; v1[i * 4 + 1] = b.y; v1[i * 4 + 2] = b.z; v1[i * 4 + 3] = b.w;
        }
        float q0[16], q1[16];
        quant16f(v0, q0);
        quant16f(v1, q1);
#pragma unroll
        for (int j = 0; j < 16; ++j)
            buf[wb * 16 + j][cp] = pack_e4m3_x2(q0[j], q1[j]);
    }
    __syncthreads();

    uint8_t* orow = xq + (((size_t)n * HW + h) * HW) * C_IN;
#pragma unroll
    for (int i = 0; i < 4; ++i) {
        int idx = t + 256 * i;
        int p   = idx >> 4;
        int qd  = idx & 15;
        uint4 val = *reinterpret_cast<const uint4*>(&buf[p][qd * 8]);
        *reinterpret_cast<uint4*>(orow + (size_t)p * C_IN + qd * 16) = val;
    }
}

// ---------------- w quant + repack -> [rs][k][c] fp8 (proven) ----------------
__global__ void quant_w_repack(const float* __restrict__ w,
                               uint8_t* __restrict__ wq2) {
    int b = blockIdx.x * blockDim.x + threadIdx.x;
    if (b >= NWBLK) return;
    const float4* src = reinterpret_cast<const float4*>(w) + (size_t)b * 4;
    float4 t0 = src[0], t1 = src[1], t2 = src[2], t3 = src[3];
    float v[16] = {t0.x, t0.y, t0.z, t0.w, t1.x, t1.y, t1.z, t1.w,
                   t2.x, t2.y, t2.z, t2.w, t3.x, t3.y, t3.z, t3.w};
    float q[16];
    quant16f(v, q);
#pragma unroll
    for (int i = 0; i < 16; ++i) {
        int f  = b * 16 + i;
        int k  = f / 2304;
        int r2 = f - k * 2304;
        int c  = r2 / 9;
        int rs = r2 - c * 9;
        wq2[((size_t)rs * K_OUT + k) * C_IN + c] = f32_to_e4m3(q[i]);
    }
}

// ---------------- winograd weight transform (proven) ----------------
__global__ void __launch_bounds__(256)
wg_transform(const uint8_t* __restrict__ wq2, __half* __restrict__ gt) {
    int k = blockIdx.x;
    int c = threadIdx.x;
    float w9[9];
#pragma unroll
    for (int rs = 0; rs < 9; ++rs)
        w9[rs] = e4m3_to_f32(wq2[((size_t)rs * K_OUT + k) * C_IN + c]);
    float a[4][3];
#pragma unroll
    for (int j = 0; j < 3; ++j) {
        float w0 = w9[0 * 3 + j], w1 = w9[1 * 3 + j], w2 = w9[2 * 3 + j];
        a[0][j] = w0;
        a[1][j] = 0.5f * (w0 + w1 + w2);
        a[2][j] = 0.5f * (w0 - w1 + w2);
        a[3][j] = w2;
    }
#pragma unroll
    for (int i = 0; i < 4; ++i) {
        float u0 = a[i][0], u1 = a[i][1], u2 = a[i][2];
        float u[4] = {u0, 0.5f * (u0 + u1 + u2), 0.5f * (u0 - u1 + u2), u2};
#pragma unroll
        for (int j = 0; j < 4; ++j)
            gt[((size_t)(i * 4 + j) * K_OUT + k) * C_IN + c] = __float2half(u[j]);
    }
}

// ---------------- cp.async helpers ----------------
__device__ __forceinline__ void cp_async16(void* dst, const void* src, bool pred) {
    uint32_t d = (uint32_t)__cvta_generic_to_shared(dst);
    int sz = pred ? 16 : 0;
    asm volatile("cp.async.cg.shared.global [%0], [%1], 16, %2;\n"
                 :: "r"(d), "l"(src), "r"(sz));
}
__device__ __forceinline__ void cp_commit() {
    asm volatile("cp.async.commit_group;\n");
}
template <int N>
__device__ __forceinline__ void cp_wait() {
    asm volatile("cp.async.wait_group %0;\n" :: "n"(N));
}

// ---------------- winograd data transform (proven, 46us) ----------------
__global__ void __launch_bounds__(256)
dt_transform(const uint8_t* __restrict__ xq, __half* __restrict__ dt) {
    extern __shared__ uint8_t sx[];
    const int n  = blockIdx.x;
    const int th = blockIdx.y;
    const int t  = threadIdx.x;

#pragma unroll
    for (int i = 0; i < 16; ++i) {
        int idx = t + 256 * i;
        int h1  = idx >> 10;
        int rem = idx & 1023;
        int w   = rem >> 4;
        int cq  = rem & 15;
        int gh  = th * 2 - 1 + h1;
        bool ok = (unsigned)gh < (unsigned)HW;
        cp_async16(sx + ((size_t)h1 * 64 + w) * 256 + cq * 16,
                   xq + (((size_t)n * HW + (ok ? gh : 0)) * HW + w) * C_IN + cq * 16, ok);
    }
    cp_commit();
    cp_wait<0>();
    __syncthreads();

    const int cp  = t & 127;
    const int twh = t >> 7;
    const __half2 zero = __floats2half2_rn(0.f, 0.f);

#pragma unroll 1
    for (int j = 0; j < 16; ++j) {
        int tw = j * 2 + twh;
        __half2 d[4][4];
#pragma unroll
        for (int wi = 0; wi < 4; ++wi) {
            int w = 2 * tw - 1 + wi;
            bool ok = (unsigned)w < (unsigned)HW;
#pragma unroll
            for (int h1 = 0; h1 < 4; ++h1) {
                if (ok) {
                    uint16_t u = *reinterpret_cast<const uint16_t*>(
                        sx + ((size_t)h1 * 64 + w) * 256 + 2 * cp);
                    uint32_t h2;
                    asm("cvt.rn.f16x2.e4m3x2 %0, %1;" : "=r"(h2) : "h"(u));
                    d[h1][wi] = *reinterpret_cast<__half2*>(&h2);
                } else {
                    d[h1][wi] = zero;
                }
            }
        }
        __half2 e[4][4];
#pragma unroll
        for (int h1 = 0; h1 < 4; ++h1) {
            e[h1][0] = __hsub2(d[h1][0], d[h1][2]);
            e[h1][1] = __hadd2(d[h1][1], d[h1][2]);
            e[h1][2] = __hsub2(d[h1][2], d[h1][1]);
            e[h1][3] = __hsub2(d[h1][1], d[h1][3]);
        }
        size_t tb = ((size_t)n * TILES_PER_IMG + th * NTILE + tw) * C_IN + 2 * cp;
#pragma unroll
        for (int jj = 0; jj < 4; ++jj) {
            __half2 D[4];
            D[0] = __hsub2(e[0][jj], e[2][jj]);
            D[1] = __hadd2(e[1][jj], e[2][jj]);
            D[2] = __hsub2(e[2][jj], e[1][jj]);
            D[3] = __hsub2(e[1][jj], e[3][jj]);
#pragma unroll
            for (int ii = 0; ii < 4; ++ii)
                *reinterpret_cast<uint32_t*>(&dt[(size_t)(ii * 4 + jj) * DT_POS_STRIDE + tb]) =
                    *reinterpret_cast<uint32_t*>(&D[ii]);
        }
    }
}

// ---------------- ldsm / mma ----------------
__device__ __forceinline__ void ldsm_x4(uint32_t addr, uint32_t& r0, uint32_t& r1,
                                        uint32_t& r2, uint32_t& r3) {
    asm volatile("ldmatrix.sync.aligned.m8n8.x4.shared.b16 {%0,%1,%2,%3}, [%4];"
                 : "=r"(r0), "=r"(r1), "=r"(r2), "=r"(r3) : "r"(addr));
}
__device__ __forceinline__ void mma16816f16(float* d, const uint32_t* a,
                                            uint32_t b0, uint32_t b1) {
    asm volatile("mma.sync.aligned.m16n8k16.row.col.f32.f16.f16.f32 "
                 "{%0,%1,%2,%3}, {%4,%5,%6,%7}, {%8,%9}, {%0,%1,%2,%3};"
                 : "+f"(d[0]), "+f"(d[1]), "+f"(d[2]), "+f"(d[3])
                 : "r"(a[0]), "r"(a[1]), "r"(a[2]), "r"(a[3]), "r"(b0), "r"(b1));
}

// ---------------- batched winograd GEMM v4: 64-channel chunks ----------------
// CTA: 256k x 128t, one pos. 256 thr, 8 warps (4 wk x 2 wt), warp 64k x 64t.
// K-chunk = 64 channels -> only 4 chunks, 8 barriers/CTA (4x fewer than v3).
// smem row = 64c = 128B data, pitch 144B (pad) -> conflict-free ldsm & stores.
#define GROWS   384
#define GPITCH  144
#define GSTAGE  (GROWS * GPITCH)    // 55296
#define GSMEM   (2 * GSTAGE)        // 110592
#define KCHUNK  64
#define NCHUNK  (C_IN / KCHUNK)     // 4

__device__ __forceinline__ void gemm_stage(char* base,
                                           const __half* __restrict__ gt,
                                           const __half* __restrict__ dt,
                                           int pos, int t0, int cc, int t) {
#pragma unroll
    for (int i = 0; i < 12; ++i) {
        int u    = t + 256 * i;               // 0..3071
        int row  = u >> 3;                    // 0..383
        int seg  = u & 7;                     // 16B segment within 128B row
        const void* src;
        if (row < 256)
            src = gt + ((size_t)pos * K_OUT + row) * C_IN + cc + seg * 8;
        else
            src = dt + (size_t)pos * DT_POS_STRIDE
                     + (size_t)(t0 + row - 256) * C_IN + cc + seg * 8;
        cp_async16(base + row * GPITCH + seg * 16, src, true);
    }
}

__global__ void __launch_bounds__(256, 1)
wino_gemm(const __half* __restrict__ gt, const __half* __restrict__ dt,
          __half* __restrict__ mt) {
    extern __shared__ char smem[];
    const int tt  = blockIdx.x;               // 0..255
    const int pos = blockIdx.y;               // 0..15
    const int t0 = tt * 128;

    const int t    = threadIdx.x;
    const int lane = t & 31;
    const int warp = t >> 5;
    const int wk   = warp & 3;                // 64-k group
    const int wt   = warp >> 2;               // 64-t group

    float acc[4][8][4];
#pragma unroll
    for (int i = 0; i < 4; ++i)
#pragma unroll
        for (int j = 0; j < 8; ++j)
#pragma unroll
            for (int v = 0; v < 4; ++v) acc[i][j][v] = 0.0f;

    gemm_stage(smem, gt, dt, pos, t0, 0, t);
    cp_commit();

    const uint32_t su = (uint32_t)__cvta_generic_to_shared(smem);
    const int a_off = (lane & 15) * GPITCH + (lane >> 4) * 16;
    const int b_off = ((lane & 7) + (lane >> 4) * 8) * GPITCH + ((lane >> 3) & 1) * 16;

#pragma unroll 1
    for (int it = 0; it < NCHUNK; ++it) {
        const int cur = it & 1;
        if (it + 1 < NCHUNK) {
            gemm_stage(smem + (cur ^ 1) * GSTAGE, gt, dt, pos, t0,
                       (it + 1) * KCHUNK, t);
            cp_commit();
            cp_wait<1>();
        } else {
            cp_wait<0>();
        }
        __syncthreads();

        const uint32_t sA = su + cur * GSTAGE;
        const uint32_t sB = sA + 256 * GPITCH;

#pragma unroll
        for (int sc = 0; sc < 4; ++sc) {
            const int cb = sc * 32;            // 16-channel sub-block byte offset
            uint32_t a[4][4];
#pragma unroll
            for (int i = 0; i < 4; ++i)
                ldsm_x4(sA + (wk * 64 + i * 16) * GPITCH + cb + a_off,
                        a[i][0], a[i][1], a[i][2], a[i][3]);
#pragma unroll
            for (int j = 0; j < 4; ++j) {
                uint32_t b[4];
                ldsm_x4(sB + (wt * 64 + j * 16) * GPITCH + cb + b_off,
                        b[0], b[1], b[2], b[3]);
#pragma unroll
                for (int i = 0; i < 4; ++i) {
                    mma16816f16(acc[i][2 * j],     a[i], b[0], b[1]);
                    mma16816f16(acc[i][2 * j + 1], a[i], b[2], b[3]);
                }
            }
        }
        __syncthreads();
    }

    // epilogue: fp16 M, layout [pos][k][gtile]
    const int g  = lane >> 2;
    const int tc = lane & 3;
    __half* mbase = mt + (size_t)pos * MT_POS_STRIDE;
#pragma unroll
    for (int i = 0; i < 4; ++i) {
        const int krow = wk * 64 + i * 16 + g;
#pragma unroll
        for (int j = 0; j < 8; ++j) {
            const int tcol = t0 + wt * 64 + j * 8 + 2 * tc;
            __half2 v0 = __floats2half2_rn(acc[i][j][0], acc[i][j][1]);
            __half2 v1 = __floats2half2_rn(acc[i][j][2], acc[i][j][3]);
            *reinterpret_cast<__half2*>(&mbase[(size_t)krow * NTILES_ALL + tcol]) = v0;
            *reinterpret_cast<__half2*>(&mbase[(size_t)(krow + 8) * NTILES_ALL + tcol]) = v1;
        }
    }
}

// ---------------- inverse transform: y = A^T M A (memory-bound) ----------------
__global__ void __launch_bounds__(256)
wino_inverse(const __half* __restrict__ mt, float* __restrict__ out) {
    const size_t idx = (size_t)blockIdx.x * 256 + threadIdx.x;   // 8.4M
    const int gtile = (int)(idx & (NTILES_ALL - 1));
    const int k     = (int)(idx >> 15);

    float m[16];
#pragma unroll
    for (int p = 0; p < 16; ++p)
        m[p] = __half2float(__ldg(&mt[(size_t)p * MT_POS_STRIDE
                                      + (size_t)k * NTILES_ALL + gtile]));

    float z0[4], z1[4];
#pragma unroll
    for (int i = 0; i < 4; ++i) {
        z0[i] = m[i * 4 + 0] + m[i * 4 + 1] + m[i * 4 + 2];
        z1[i] = m[i * 4 + 1] - m[i * 4 + 2] - m[i * 4 + 3];
    }
    float y00 = z0[0] + z0[1] + z0[2];
    float y01 = z1[0] + z1[1] + z1[2];
    float y10 = z0[1] - z0[2] - z0[3];
    float y11 = z1[1] - z1[2] - z1[3];

    const int n  = gtile >> 10;
    const int th = (gtile >> 5) & 31;
    const int tw = gtile & 31;
    size_t ob = (((size_t)n * K_OUT + k) * HW + 2 * th) * HW + 2 * tw;
    *reinterpret_cast<float2*>(out + ob)      = make_float2(y00, y01);
    *reinterpret_cast<float2*>(out + ob + HW) = make_float2(y10, y11);
}

// ---------------- launch ----------------
extern "C" void kernel_launch(void* const* d_in, const int* in_sizes, int n_in,
                              void* d_out, int out_size) {
    const float* x = (const float*)d_in[0];
    const float* w = (const float*)d_in[1];
    if (in_sizes[0] != X_ELEMS) {
        x = (const float*)d_in[1];
        w = (const float*)d_in[0];
    }

    void *xq_p, *wq_p, *gt_p, *dt_p, *mt_p;
    cudaGetSymbolAddress(&xq_p, g_xq);
    cudaGetSymbolAddress(&wq_p, g_wq2);
    cudaGetSymbolAddress(&gt_p, g_gt);
    cudaGetSymbolAddress(&dt_p, g_dt);
    cudaGetSymbolAddress(&mt_p, g_mt);
    uint8_t* xq  = (uint8_t*)xq_p;
    uint8_t* wq2 = (uint8_t*)wq_p;
    __half*  gt  = (__half*)gt_p;
    __half*  dt  = (__half*)dt_p;
    __half*  mt  = (__half*)mt_p;

    cudaFuncSetAttribute(dt_transform,
                         cudaFuncAttributeMaxDynamicSharedMemorySize, 65536);
    cudaFuncSetAttribute(wino_gemm,
                         cudaFuncAttributeMaxDynamicSharedMemorySize, GSMEM);

    quant_x_nhwc<<<dim3(N_IMG, HW), 256>>>(x, xq);
    quant_w_repack<<<(NWBLK + 255) / 256, 256>>>(w, wq2);
    wg_transform<<<K_OUT, C_IN>>>(wq2, gt);
    dt_transform<<<dim3(N_IMG, NTILE), 256, 65536>>>(xq, dt);
    wino_gemm<<<dim3(256, 16), 256, GSMEM>>>(gt, dt, mt);
    wino_inverse<<<NTILES_ALL, 256>>>(mt, (float*)d_out);
}

// round 14
// speedup vs baseline: 1.3381x; 1.0964x over previous
#include <cuda_runtime.h>
#include <cuda_fp16.h>
#include <cstdint>

// ---------------- problem constants ----------------
#define N_IMG   32
#define C_IN    256
#define HW      64
#define K_OUT   256
#define X_ELEMS (N_IMG * C_IN * HW * HW)          // 33554432
#define W_ELEMS (K_OUT * C_IN * 9)                // 589824
#define NWBLK   (W_ELEMS / 16)                    // 36864
#define NTILE   32
#define TILES_PER_IMG (NTILE * NTILE)             // 1024
#define NTILES_ALL (N_IMG * TILES_PER_IMG)        // 32768
#define DT_POS_STRIDE ((size_t)NTILES_ALL * C_IN) // 8388608
#define MT_POS_STRIDE ((size_t)K_OUT * NTILES_ALL)// 8388608

// ---------------- scratch ----------------
__device__ uint8_t g_xq[X_ELEMS];                     // NHWC fp8 (exact quantized)
__device__ uint8_t g_wq2[9 * K_OUT * C_IN];           // [rs][k][c] fp8 (exact)
__device__ __half  g_gt[16 * K_OUT * C_IN];           // winograd weights fp16
__device__ __half  g_dt[16ull * DT_POS_STRIDE];       // winograd data fp16
__device__ __half  g_mt[16ull * MT_POS_STRIDE];       // winograd product fp16

// ---------------- fp8 helpers ----------------
__device__ __forceinline__ uint16_t pack_e4m3_x2(float lo, float hi) {
    uint16_t r;
    asm volatile("cvt.rn.satfinite.e4m3x2.f32 %0, %1, %2;" : "=h"(r) : "f"(hi), "f"(lo));
    return r;
}
__device__ __forceinline__ uint8_t f32_to_e4m3(float v) {
    uint16_t r;
    asm volatile("cvt.rn.satfinite.e4m3x2.f32 %0, %1, %2;" : "=h"(r) : "f"(0.0f), "f"(v));
    return (uint8_t)(r & 0xFF);
}
__device__ __forceinline__ float e4m3_to_f32(uint8_t b) {
    uint16_t s = b;
    uint32_t h2;
    asm("cvt.rn.f16x2.e4m3x2 %0, %1;" : "=r"(h2) : "h"(s));
    __half lo = __ushort_as_half((uint16_t)(h2 & 0xFFFF));
    return __half2float(lo);
}

// ---------------- fake-quant core (exact pow2 scale + RTN E2M1) ----------------
__device__ __forceinline__ void quant16f(const float* __restrict__ v,
                                         float* __restrict__ q) {
    float amax = 0.0f;
#pragma unroll
    for (int i = 0; i < 16; ++i) amax = fmaxf(amax, fabsf(v[i]));
    float scale = 1.0f;
    if (amax > 0.0f) {
        float y = fmaxf(amax, 1e-30f) / 6.0f;
        int e;
        float m = frexpf(y, &e);
        scale = ldexpf(1.0f, (m == 0.5f) ? (e - 1) : e);
    }
    float inv = 1.0f / scale;
#pragma unroll
    for (int i = 0; i < 16; ++i) {
        float u = v[i] * inv;
        float a = fabsf(u);
        float g;
        if      (a < 0.25f) g = 0.0f;
        else if (a < 0.75f) g = 0.5f;
        else if (a < 1.25f) g = 1.0f;
        else if (a < 1.75f) g = 1.5f;
        else if (a < 2.5f)  g = 2.0f;
        else if (a < 3.5f)  g = 3.0f;
        else if (a < 5.0f)  g = 4.0f;
        else                g = 6.0f;
        q[i] = copysignf(g, u) * scale;     // exact in e4m3
    }
}

// ---------------- x quant -> NHWC fp8 (proven, ~51us) ----------------
__global__ void __launch_bounds__(256)
quant_x_nhwc(const float* __restrict__ x, uint8_t* __restrict__ xq) {
    __shared__ uint16_t buf[64][136];
    const int n = blockIdx.x;
    const int h = blockIdx.y;
    const int t = threadIdx.x;
    const int cp  = t & 127;
    const int wb0 = t >> 7;

#pragma unroll
    for (int wbi = 0; wbi < 2; ++wbi) {
        int wb = wb0 + wbi * 2;
        const float* base = x + (((size_t)n * C_IN + 2 * cp) * HW + h) * HW + wb * 16;
        const float4* p0 = reinterpret_cast<const float4*>(base);
        const float4* p1 = reinterpret_cast<const float4*>(base + (size_t)HW * HW);
        float v0[16], v1[16];
#pragma unroll
        for (int i = 0; i < 4; ++i) {
            float4 a = p0[i];
            v0[i * 4 + 0] = a.x; v0[i * 4 + 1] = a.y; v0[i * 4 + 2] = a.z; v0[i * 4 + 3] = a.w;
            float4 b = p1[i];
            v1[i * 4 + 0] = b.x; v1[i * 4 + 1] = b.y; v1[i * 4 + 2] = b.z; v1[i * 4 + 3] = b.w;
        }
        float q0[16], q1[16];
        quant16f(v0, q0);
        quant16f(v1, q1);
#pragma unroll
        for (int j = 0; j < 16; ++j)
            buf[wb * 16 + j][cp] = pack_e4m3_x2(q0[j], q1[j]);
    }
    __syncthreads();

    uint8_t* orow = xq + (((size_t)n * HW + h) * HW) * C_IN;
#pragma unroll
    for (int i = 0; i < 4; ++i) {
        int idx = t + 256 * i;
        int p   = idx >> 4;
        int qd  = idx & 15;
        uint4 val = *reinterpret_cast<const uint4*>(&buf[p][qd * 8]);
        *reinterpret_cast<uint4*>(orow + (size_t)p * C_IN + qd * 16) = val;
    }
}

// ---------------- w quant + repack -> [rs][k][c] fp8 (proven) ----------------
__global__ void quant_w_repack(const float* __restrict__ w,
                               uint8_t* __restrict__ wq2) {
    int b = blockIdx.x * blockDim.x + threadIdx.x;
    if (b >= NWBLK) return;
    const float4* src = reinterpret_cast<const float4*>(w) + (size_t)b * 4;
    float4 t0 = src[0], t1 = src[1], t2 = src[2], t3 = src[3];
    float v[16] = {t0.x, t0.y, t0.z, t0.w, t1.x, t1.y, t1.z, t1.w,
                   t2.x, t2.y, t2.z, t2.w, t3.x, t3.y, t3.z, t3.w};
    float q[16];
    quant16f(v, q);
#pragma unroll
    for (int i = 0; i < 16; ++i) {
        int f  = b * 16 + i;
        int k  = f / 2304;
        int r2 = f - k * 2304;
        int c  = r2 / 9;
        int rs = r2 - c * 9;
        wq2[((size_t)rs * K_OUT + k) * C_IN + c] = f32_to_e4m3(q[i]);
    }
}

// ---------------- winograd weight transform (proven) ----------------
__global__ void __launch_bounds__(256)
wg_transform(const uint8_t* __restrict__ wq2, __half* __restrict__ gt) {
    int k = blockIdx.x;
    int c = threadIdx.x;
    float w9[9];
#pragma unroll
    for (int rs = 0; rs < 9; ++rs)
        w9[rs] = e4m3_to_f32(wq2[((size_t)rs * K_OUT + k) * C_IN + c]);
    float a[4][3];
#pragma unroll
    for (int j = 0; j < 3; ++j) {
        float w0 = w9[0 * 3 + j], w1 = w9[1 * 3 + j], w2 = w9[2 * 3 + j];
        a[0][j] = w0;
        a[1][j] = 0.5f * (w0 + w1 + w2);
        a[2][j] = 0.5f * (w0 - w1 + w2);
        a[3][j] = w2;
    }
#pragma unroll
    for (int i = 0; i < 4; ++i) {
        float u0 = a[i][0], u1 = a[i][1], u2 = a[i][2];
        float u[4] = {u0, 0.5f * (u0 + u1 + u2), 0.5f * (u0 - u1 + u2), u2};
#pragma unroll
        for (int j = 0; j < 4; ++j)
            gt[((size_t)(i * 4 + j) * K_OUT + k) * C_IN + c] = __float2half(u[j]);
    }
}

// ---------------- cp.async helpers ----------------
__device__ __forceinline__ void cp_async16(void* dst, const void* src, bool pred) {
    uint32_t d = (uint32_t)__cvta_generic_to_shared(dst);
    int sz = pred ? 16 : 0;
    asm volatile("cp.async.cg.shared.global [%0], [%1], 16, %2;\n"
                 :: "r"(d), "l"(src), "r"(sz));
}
__device__ __forceinline__ void cp_commit() {
    asm volatile("cp.async.commit_group;\n");
}
template <int N>
__device__ __forceinline__ void cp_wait() {
    asm volatile("cp.async.wait_group %0;\n" :: "n"(N));
}

// ---------------- winograd data transform (proven, 46us) ----------------
__global__ void __launch_bounds__(256)
dt_transform(const uint8_t* __restrict__ xq, __half* __restrict__ dt) {
    extern __shared__ uint8_t sx[];
    const int n  = blockIdx.x;
    const int th = blockIdx.y;
    const int t  = threadIdx.x;

#pragma unroll
    for (int i = 0; i < 16; ++i) {
        int idx = t + 256 * i;
        int h1  = idx >> 10;
        int rem = idx & 1023;
        int w   = rem >> 4;
        int cq  = rem & 15;
        int gh  = th * 2 - 1 + h1;
        bool ok = (unsigned)gh < (unsigned)HW;
        cp_async16(sx + ((size_t)h1 * 64 + w) * 256 + cq * 16,
                   xq + (((size_t)n * HW + (ok ? gh : 0)) * HW + w) * C_IN + cq * 16, ok);
    }
    cp_commit();
    cp_wait<0>();
    __syncthreads();

    const int cp  = t & 127;
    const int twh = t >> 7;
    const __half2 zero = __floats2half2_rn(0.f, 0.f);

#pragma unroll 1
    for (int j = 0; j < 16; ++j) {
        int tw = j * 2 + twh;
        __half2 d[4][4];
#pragma unroll
        for (int wi = 0; wi < 4; ++wi) {
            int w = 2 * tw - 1 + wi;
            bool ok = (unsigned)w < (unsigned)HW;
#pragma unroll
            for (int h1 = 0; h1 < 4; ++h1) {
                if (ok) {
                    uint16_t u = *reinterpret_cast<const uint16_t*>(
                        sx + ((size_t)h1 * 64 + w) * 256 + 2 * cp);
                    uint32_t h2;
                    asm("cvt.rn.f16x2.e4m3x2 %0, %1;" : "=r"(h2) : "h"(u));
                    d[h1][wi] = *reinterpret_cast<__half2*>(&h2);
                } else {
                    d[h1][wi] = zero;
                }
            }
        }
        __half2 e[4][4];
#pragma unroll
        for (int h1 = 0; h1 < 4; ++h1) {
            e[h1][0] = __hsub2(d[h1][0], d[h1][2]);
            e[h1][1] = __hadd2(d[h1][1], d[h1][2]);
            e[h1][2] = __hsub2(d[h1][2], d[h1][1]);
            e[h1][3] = __hsub2(d[h1][1], d[h1][3]);
        }
        size_t tb = ((size_t)n * TILES_PER_IMG + th * NTILE + tw) * C_IN + 2 * cp;
#pragma unroll
        for (int jj = 0; jj < 4; ++jj) {
            __half2 D[4];
            D[0] = __hsub2(e[0][jj], e[2][jj]);
            D[1] = __hadd2(e[1][jj], e[2][jj]);
            D[2] = __hsub2(e[2][jj], e[1][jj]);
            D[3] = __hsub2(e[1][jj], e[3][jj]);
#pragma unroll
            for (int ii = 0; ii < 4; ++ii)
                *reinterpret_cast<uint32_t*>(&dt[(size_t)(ii * 4 + jj) * DT_POS_STRIDE + tb]) =
                    *reinterpret_cast<uint32_t*>(&D[ii]);
        }
    }
}

// ---------------- ldsm / mma ----------------
__device__ __forceinline__ void ldsm_x4(uint32_t addr, uint32_t& r0, uint32_t& r1,
                                        uint32_t& r2, uint32_t& r3) {
    asm volatile("ldmatrix.sync.aligned.m8n8.x4.shared.b16 {%0,%1,%2,%3}, [%4];"
                 : "=r"(r0), "=r"(r1), "=r"(r2), "=r"(r3) : "r"(addr));
}
__device__ __forceinline__ void mma16816f16(float* d, const uint32_t* a,
                                            uint32_t b0, uint32_t b1) {
    asm volatile("mma.sync.aligned.m16n8k16.row.col.f32.f16.f16.f32 "
                 "{%0,%1,%2,%3}, {%4,%5,%6,%7}, {%8,%9}, {%0,%1,%2,%3};"
                 : "+f"(d[0]), "+f"(d[1]), "+f"(d[2]), "+f"(d[3])
                 : "r"(a[0]), "r"(a[1]), "r"(a[2]), "r"(a[3]), "r"(b0), "r"(b1));
}

// ---------------- batched winograd GEMM v5: 64c chunks, 3-stage pipeline ------
// CTA: 256k x 128t, one pos. 256 thr, 8 warps (4 wk x 2 wt), warp 64k x 64t.
// smem row = 64c = 128B data, pitch 144B (pad) -> conflict-free ldsm & stores.
#define GROWS   384
#define GPITCH  144
#define GSTAGE  (GROWS * GPITCH)    // 55296
#define NGSTAGE 3
#define GSMEM   (NGSTAGE * GSTAGE)  // 165888
#define KCHUNK  64
#define NCHUNK  (C_IN / KCHUNK)     // 4

__device__ __forceinline__ void gemm_stage(char* base,
                                           const __half* __restrict__ gt,
                                           const __half* __restrict__ dt,
                                           int pos, int t0, int cc, int t) {
#pragma unroll
    for (int i = 0; i < 12; ++i) {
        int u    = t + 256 * i;               // 0..3071
        int row  = u >> 3;                    // 0..383
        int seg  = u & 7;                     // 16B segment within 128B row
        const void* src;
        if (row < 256)
            src = gt + ((size_t)pos * K_OUT + row) * C_IN + cc + seg * 8;
        else
            src = dt + (size_t)pos * DT_POS_STRIDE
                     + (size_t)(t0 + row - 256) * C_IN + cc + seg * 8;
        cp_async16(base + row * GPITCH + seg * 16, src, true);
    }
}

__global__ void __launch_bounds__(256, 1)
wino_gemm(const __half* __restrict__ gt, const __half* __restrict__ dt,
          __half* __restrict__ mt) {
    extern __shared__ char smem[];
    const int tt  = blockIdx.x;               // 0..255
    const int pos = blockIdx.y;               // 0..15
    const int t0 = tt * 128;

    const int t    = threadIdx.x;
    const int lane = t & 31;
    const int warp = t >> 5;
    const int wk   = warp & 3;                // 64-k group
    const int wt   = warp >> 2;               // 64-t group

    float acc[4][8][4];
#pragma unroll
    for (int i = 0; i < 4; ++i)
#pragma unroll
        for (int j = 0; j < 8; ++j)
#pragma unroll
            for (int v = 0; v < 4; ++v) acc[i][j][v] = 0.0f;

    // prologue: stages 0,1
    gemm_stage(smem + 0 * GSTAGE, gt, dt, pos, t0, 0 * KCHUNK, t);
    cp_commit();
    gemm_stage(smem + 1 * GSTAGE, gt, dt, pos, t0, 1 * KCHUNK, t);
    cp_commit();

    const uint32_t su = (uint32_t)__cvta_generic_to_shared(smem);
    const int a_off = (lane & 15) * GPITCH + (lane >> 4) * 16;
    const int b_off = ((lane & 7) + (lane >> 4) * 8) * GPITCH + ((lane >> 3) & 1) * 16;

    int cur = 0, nxt2 = 2;
#pragma unroll 1
    for (int it = 0; it < NCHUNK; ++it) {
        __syncthreads();   // all warps finished reading the buffer stage it+2 reuses

        if (it + 2 < NCHUNK) {
            gemm_stage(smem + nxt2 * GSTAGE, gt, dt, pos, t0, (it + 2) * KCHUNK, t);
            cp_commit();
            cp_wait<2>();                      // stage it complete
        } else if (it + 1 < NCHUNK) {
            cp_wait<1>();
        } else {
            cp_wait<0>();
        }
        __syncthreads();   // stage it visible to all warps

        const uint32_t sA = su + cur * GSTAGE;
        const uint32_t sB = sA + 256 * GPITCH;

#pragma unroll
        for (int sc = 0; sc < 4; ++sc) {
            const int cb = sc * 32;            // 16-channel sub-block byte offset
            uint32_t a[4][4];
#pragma unroll
            for (int i = 0; i < 4; ++i)
                ldsm_x4(sA + (wk * 64 + i * 16) * GPITCH + cb + a_off,
                        a[i][0], a[i][1], a[i][2], a[i][3]);
#pragma unroll
            for (int j = 0; j < 4; ++j) {
                uint32_t b[4];
                ldsm_x4(sB + (wt * 64 + j * 16) * GPITCH + cb + b_off,
                        b[0], b[1], b[2], b[3]);
#pragma unroll
                for (int i = 0; i < 4; ++i) {
                    mma16816f16(acc[i][2 * j],     a[i], b[0], b[1]);
                    mma16816f16(acc[i][2 * j + 1], a[i], b[2], b[3]);
                }
            }
        }
        cur  = (cur + 1 == NGSTAGE) ? 0 : cur + 1;
        nxt2 = (nxt2 + 1 == NGSTAGE) ? 0 : nxt2 + 1;
    }

    // epilogue: fp16 M, layout [pos][k][gtile]
    const int g  = lane >> 2;
    const int tc = lane & 3;
    __half* mbase = mt + (size_t)pos * MT_POS_STRIDE;
#pragma unroll
    for (int i = 0; i < 4; ++i) {
        const int krow = wk * 64 + i * 16 + g;
#pragma unroll
        for (int j = 0; j < 8; ++j) {
            const int tcol = t0 + wt * 64 + j * 8 + 2 * tc;
            __half2 v0 = __floats2half2_rn(acc[i][j][0], acc[i][j][1]);
            __half2 v1 = __floats2half2_rn(acc[i][j][2], acc[i][j][3]);
            *reinterpret_cast<__half2*>(&mbase[(size_t)krow * NTILES_ALL + tcol]) = v0;
            *reinterpret_cast<__half2*>(&mbase[(size_t)(krow + 8) * NTILES_ALL + tcol]) = v1;
        }
    }
}

// ---------------- inverse transform v2: 2 gtiles/thread, vectorized ----------
__global__ void __launch_bounds__(256)
wino_inverse(const __half* __restrict__ mt, float* __restrict__ out) {
    const size_t idx = (size_t)blockIdx.x * 256 + threadIdx.x;   // 4.2M
    const int gp = (int)(idx & (NTILES_ALL / 2 - 1));            // gtile pair
    const int k  = (int)(idx >> 14);
    const int gtile0 = gp * 2;

    float m0[16], m1[16];
#pragma unroll
    for (int p = 0; p < 16; ++p) {
        __half2 hv = *reinterpret_cast<const __half2*>(
            &mt[(size_t)p * MT_POS_STRIDE + (size_t)k * NTILES_ALL + gtile0]);
        float2 fv = __half22float2(hv);
        m0[p] = fv.x;
        m1[p] = fv.y;
    }

    float z0a[4], z1a[4], z0b[4], z1b[4];
#pragma unroll
    for (int i = 0; i < 4; ++i) {
        z0a[i] = m0[i * 4 + 0] + m0[i * 4 + 1] + m0[i * 4 + 2];
        z1a[i] = m0[i * 4 + 1] - m0[i * 4 + 2] - m0[i * 4 + 3];
        z0b[i] = m1[i * 4 + 0] + m1[i * 4 + 1] + m1[i * 4 + 2];
        z1b[i] = m1[i * 4 + 1] - m1[i * 4 + 2] - m1[i * 4 + 3];
    }
    // tile0 outputs (cols 2tw,2tw+1), tile1 outputs (cols 2tw+2,2tw+3)
    float4 r0 = make_float4(z0a[0] + z0a[1] + z0a[2],  // y00 t0
                            z1a[0] + z1a[1] + z1a[2],  // y01 t0
                            z0b[0] + z0b[1] + z0b[2],  // y00 t1
                            z1b[0] + z1b[1] + z1b[2]); // y01 t1
    float4 r1 = make_float4(z0a[1] - z0a[2] - z0a[3],
                            z1a[1] - z1a[2] - z1a[3],
                            z0b[1] - z0b[2] - z0b[3],
                            z1b[1] - z1b[2] - z1b[3]);

    const int n  = gtile0 >> 10;
    const int th = (gtile0 >> 5) & 31;
    const int tw = gtile0 & 31;              // even
    size_t ob = (((size_t)n * K_OUT + k) * HW + 2 * th) * HW + 2 * tw;
    *reinterpret_cast<float4*>(out + ob)      = r0;
    *reinterpret_cast<float4*>(out + ob + HW) = r1;
}

// ---------------- launch ----------------
extern "C" void kernel_launch(void* const* d_in, const int* in_sizes, int n_in,
                              void* d_out, int out_size) {
    const float* x = (const float*)d_in[0];
    const float* w = (const float*)d_in[1];
    if (in_sizes[0] != X_ELEMS) {
        x = (const float*)d_in[1];
        w = (const float*)d_in[0];
    }

    void *xq_p, *wq_p, *gt_p, *dt_p, *mt_p;
    cudaGetSymbolAddress(&xq_p, g_xq);
    cudaGetSymbolAddress(&wq_p, g_wq2);
    cudaGetSymbolAddress(&gt_p, g_gt);
    cudaGetSymbolAddress(&dt_p, g_dt);
    cudaGetSymbolAddress(&mt_p, g_mt);
    uint8_t* xq  = (uint8_t*)xq_p;
    uint8_t* wq2 = (uint8_t*)wq_p;
    __half*  gt  = (__half*)gt_p;
    __half*  dt  = (__half*)dt_p;
    __half*  mt  = (__half*)mt_p;

    cudaFuncSetAttribute(dt_transform,
                         cudaFuncAttributeMaxDynamicSharedMemorySize, 65536);
    cudaFuncSetAttribute(wino_gemm,
                         cudaFuncAttributeMaxDynamicSharedMemorySize, GSMEM);

    quant_x_nhwc<<<dim3(N_IMG, HW), 256>>>(x, xq);
    quant_w_repack<<<(NWBLK + 255) / 256, 256>>>(w, wq2);
    wg_transform<<<K_OUT, C_IN>>>(wq2, gt);
    dt_transform<<<dim3(N_IMG, NTILE), 256, 65536>>>(xq, dt);
    wino_gemm<<<dim3(256, 16), 256, GSMEM>>>(gt, dt, mt);
    wino_inverse<<<K_OUT * NTILES_ALL / 2 / 256, 256>>>(mt, (float*)d_out);
}

// round 15
// speedup vs baseline: 1.3457x; 1.0057x over previous
#include <cuda_runtime.h>
#include <cuda_fp16.h>
#include <cstdint>

// ---------------- problem constants ----------------
#define N_IMG   32
#define C_IN    256
#define HW      64
#define K_OUT   256
#define X_ELEMS (N_IMG * C_IN * HW * HW)          // 33554432
#define W_ELEMS (K_OUT * C_IN * 9)                // 589824
#define NWBLK   (W_ELEMS / 16)                    // 36864
#define NTILE   32
#define TILES_PER_IMG (NTILE * NTILE)             // 1024
#define NTILES_ALL (N_IMG * TILES_PER_IMG)        // 32768
#define DT_POS_STRIDE ((size_t)NTILES_ALL * C_IN) // 8388608
#define MT_POS_STRIDE ((size_t)K_OUT * NTILES_ALL)// 8388608

// ---------------- scratch ----------------
__device__ uint8_t g_xq[X_ELEMS];                     // NHWC fp8 (exact quantized)
__device__ uint8_t g_wq2[9 * K_OUT * C_IN];           // [rs][k][c] fp8 (exact)
__device__ __half  g_gt[16 * K_OUT * C_IN];           // winograd weights fp16
__device__ __half  g_dt[16ull * DT_POS_STRIDE];       // winograd data fp16
__device__ __half  g_mt[16ull * MT_POS_STRIDE];       // winograd product fp16

// ---------------- fp8 helpers ----------------
__device__ __forceinline__ uint16_t pack_e4m3_x2(float lo, float hi) {
    uint16_t r;
    asm volatile("cvt.rn.satfinite.e4m3x2.f32 %0, %1, %2;" : "=h"(r) : "f"(hi), "f"(lo));
    return r;
}
__device__ __forceinline__ uint8_t f32_to_e4m3(float v) {
    uint16_t r;
    asm volatile("cvt.rn.satfinite.e4m3x2.f32 %0, %1, %2;" : "=h"(r) : "f"(0.0f), "f"(v));
    return (uint8_t)(r & 0xFF);
}
__device__ __forceinline__ float e4m3_to_f32(uint8_t b) {
    uint16_t s = b;
    uint32_t h2;
    asm("cvt.rn.f16x2.e4m3x2 %0, %1;" : "=r"(h2) : "h"(s));
    __half lo = __ushort_as_half((uint16_t)(h2 & 0xFFFF));
    return __half2float(lo);
}

// ---------------- fake-quant core (exact pow2 scale + RTN E2M1, ties-up) ------
__device__ __forceinline__ void quant16f(const float* __restrict__ v,
                                         float* __restrict__ q) {
    float amax = 0.0f;
#pragma unroll
    for (int i = 0; i < 16; ++i) amax = fmaxf(amax, fabsf(v[i]));
    float scale = 1.0f;
    if (amax > 0.0f) {
        float y = fmaxf(amax, 1e-30f) / 6.0f;
        int e;
        float m = frexpf(y, &e);
        scale = ldexpf(1.0f, (m == 0.5f) ? (e - 1) : e);
    }
    float inv = 1.0f / scale;
#pragma unroll
    for (int i = 0; i < 16; ++i) {
        float u = v[i] * inv;                 // exact (pow2)
        float a = fabsf(u);
        float g;
        if (a < 1.75f)      g = floorf(2.0f * a + 0.5f) * 0.5f;  // 0,.5,1,1.5 ties-up
        else if (a < 3.5f)  g = floorf(a + 0.5f);                // 2,3 ties-up
        else                g = (a < 5.0f) ? 4.0f : 6.0f;        // 4,6
        q[i] = copysignf(g, u) * scale;       // exact in e4m3
    }
}

// ---------------- x quant -> NHWC fp8 ----------------
__global__ void __launch_bounds__(256)
quant_x_nhwc(const float* __restrict__ x, uint8_t* __restrict__ xq) {
    __shared__ uint16_t buf[64][136];
    const int n = blockIdx.x;
    const int h = blockIdx.y;
    const int t = threadIdx.x;
    const int cp  = t & 127;
    const int wb0 = t >> 7;

#pragma unroll
    for (int wbi = 0; wbi < 2; ++wbi) {
        int wb = wb0 + wbi * 2;
        const float* base = x + (((size_t)n * C_IN + 2 * cp) * HW + h) * HW + wb * 16;
        const float4* p0 = reinterpret_cast<const float4*>(base);
        const float4* p1 = reinterpret_cast<const float4*>(base + (size_t)HW * HW);
        float v0[16], v1[16];
#pragma unroll
        for (int i = 0; i < 4; ++i) {
            float4 a = p0[i];
            v0[i * 4 + 0] = a.x; v0[i * 4 + 1] = a.y; v0[i * 4 + 2] = a.z; v0[i * 4 + 3] = a.w;
            float4 b = p1[i];
            v1[i * 4 + 0] = b.x; v1[i * 4 + 1] = b.y; v1[i * 4 + 2] = b.z; v1[i * 4 + 3] = b.w;
        }
        float q0[16], q1[16];
        quant16f(v0, q0);
        quant16f(v1, q1);
#pragma unroll
        for (int j = 0; j < 16; ++j)
            buf[wb * 16 + j][cp] = pack_e4m3_x2(q0[j], q1[j]);
    }
    __syncthreads();

    uint8_t* orow = xq + (((size_t)n * HW + h) * HW) * C_IN;
#pragma unroll
    for (int i = 0; i < 4; ++i) {
        int idx = t + 256 * i;
        int p   = idx >> 4;
        int qd  = idx & 15;
        uint4 val = *reinterpret_cast<const uint4*>(&buf[p][qd * 8]);
        *reinterpret_cast<uint4*>(orow + (size_t)p * C_IN + qd * 16) = val;
    }
}

// ---------------- w quant + repack -> [rs][k][c] fp8 ----------------
__global__ void quant_w_repack(const float* __restrict__ w,
                               uint8_t* __restrict__ wq2) {
    int b = blockIdx.x * blockDim.x + threadIdx.x;
    if (b >= NWBLK) return;
    const float4* src = reinterpret_cast<const float4*>(w) + (size_t)b * 4;
    float4 t0 = src[0], t1 = src[1], t2 = src[2], t3 = src[3];
    float v[16] = {t0.x, t0.y, t0.z, t0.w, t1.x, t1.y, t1.z, t1.w,
                   t2.x, t2.y, t2.z, t2.w, t3.x, t3.y, t3.z, t3.w};
    float q[16];
    quant16f(v, q);
#pragma unroll
    for (int i = 0; i < 16; ++i) {
        int f  = b * 16 + i;
        int k  = f / 2304;
        int r2 = f - k * 2304;
        int c  = r2 / 9;
        int rs = r2 - c * 9;
        wq2[((size_t)rs * K_OUT + k) * C_IN + c] = f32_to_e4m3(q[i]);
    }
}

// ---------------- winograd weight transform (proven) ----------------
__global__ void __launch_bounds__(256)
wg_transform(const uint8_t* __restrict__ wq2, __half* __restrict__ gt) {
    int k = blockIdx.x;
    int c = threadIdx.x;
    float w9[9];
#pragma unroll
    for (int rs = 0; rs < 9; ++rs)
        w9[rs] = e4m3_to_f32(wq2[((size_t)rs * K_OUT + k) * C_IN + c]);
    float a[4][3];
#pragma unroll
    for (int j = 0; j < 3; ++j) {
        float w0 = w9[0 * 3 + j], w1 = w9[1 * 3 + j], w2 = w9[2 * 3 + j];
        a[0][j] = w0;
        a[1][j] = 0.5f * (w0 + w1 + w2);
        a[2][j] = 0.5f * (w0 - w1 + w2);
        a[3][j] = w2;
    }
#pragma unroll
    for (int i = 0; i < 4; ++i) {
        float u0 = a[i][0], u1 = a[i][1], u2 = a[i][2];
        float u[4] = {u0, 0.5f * (u0 + u1 + u2), 0.5f * (u0 - u1 + u2), u2};
#pragma unroll
        for (int j = 0; j < 4; ++j)
            gt[((size_t)(i * 4 + j) * K_OUT + k) * C_IN + c] = __float2half(u[j]);
    }
}

// ---------------- cp.async helpers ----------------
__device__ __forceinline__ void cp_async16(void* dst, const void* src, bool pred) {
    uint32_t d = (uint32_t)__cvta_generic_to_shared(dst);
    int sz = pred ? 16 : 0;
    asm volatile("cp.async.cg.shared.global [%0], [%1], 16, %2;\n"
                 :: "r"(d), "l"(src), "r"(sz));
}
__device__ __forceinline__ void cp_commit() {
    asm volatile("cp.async.commit_group;\n");
}
template <int N>
__device__ __forceinline__ void cp_wait() {
    asm volatile("cp.async.wait_group %0;\n" :: "n"(N));
}

// ---------------- winograd data transform (proven, 46us) ----------------
__global__ void __launch_bounds__(256)
dt_transform(const uint8_t* __restrict__ xq, __half* __restrict__ dt) {
    extern __shared__ uint8_t sx[];
    const int n  = blockIdx.x;
    const int th = blockIdx.y;
    const int t  = threadIdx.x;

#pragma unroll
    for (int i = 0; i < 16; ++i) {
        int idx = t + 256 * i;
        int h1  = idx >> 10;
        int rem = idx & 1023;
        int w   = rem >> 4;
        int cq  = rem & 15;
        int gh  = th * 2 - 1 + h1;
        bool ok = (unsigned)gh < (unsigned)HW;
        cp_async16(sx + ((size_t)h1 * 64 + w) * 256 + cq * 16,
                   xq + (((size_t)n * HW + (ok ? gh : 0)) * HW + w) * C_IN + cq * 16, ok);
    }
    cp_commit();
    cp_wait<0>();
    __syncthreads();

    const int cp  = t & 127;
    const int twh = t >> 7;
    const __half2 zero = __floats2half2_rn(0.f, 0.f);

#pragma unroll 1
    for (int j = 0; j < 16; ++j) {
        int tw = j * 2 + twh;
        __half2 d[4][4];
#pragma unroll
        for (int wi = 0; wi < 4; ++wi) {
            int w = 2 * tw - 1 + wi;
            bool ok = (unsigned)w < (unsigned)HW;
#pragma unroll
            for (int h1 = 0; h1 < 4; ++h1) {
                if (ok) {
                    uint16_t u = *reinterpret_cast<const uint16_t*>(
                        sx + ((size_t)h1 * 64 + w) * 256 + 2 * cp);
                    uint32_t h2;
                    asm("cvt.rn.f16x2.e4m3x2 %0, %1;" : "=r"(h2) : "h"(u));
                    d[h1][wi] = *reinterpret_cast<__half2*>(&h2);
                } else {
                    d[h1][wi] = zero;
                }
            }
        }
        __half2 e[4][4];
#pragma unroll
        for (int h1 = 0; h1 < 4; ++h1) {
            e[h1][0] = __hsub2(d[h1][0], d[h1][2]);
            e[h1][1] = __hadd2(d[h1][1], d[h1][2]);
            e[h1][2] = __hsub2(d[h1][2], d[h1][1]);
            e[h1][3] = __hsub2(d[h1][1], d[h1][3]);
        }
        size_t tb = ((size_t)n * TILES_PER_IMG + th * NTILE + tw) * C_IN + 2 * cp;
#pragma unroll
        for (int jj = 0; jj < 4; ++jj) {
            __half2 D[4];
            D[0] = __hsub2(e[0][jj], e[2][jj]);
            D[1] = __hadd2(e[1][jj], e[2][jj]);
            D[2] = __hsub2(e[2][jj], e[1][jj]);
            D[3] = __hsub2(e[1][jj], e[3][jj]);
#pragma unroll
            for (int ii = 0; ii < 4; ++ii)
                *reinterpret_cast<uint32_t*>(&dt[(size_t)(ii * 4 + jj) * DT_POS_STRIDE + tb]) =
                    *reinterpret_cast<uint32_t*>(&D[ii]);
        }
    }
}

// ---------------- ldsm / mma ----------------
__device__ __forceinline__ void ldsm_x4(uint32_t addr, uint32_t& r0, uint32_t& r1,
                                        uint32_t& r2, uint32_t& r3) {
    asm volatile("ldmatrix.sync.aligned.m8n8.x4.shared.b16 {%0,%1,%2,%3}, [%4];"
                 : "=r"(r0), "=r"(r1), "=r"(r2), "=r"(r3) : "r"(addr));
}
__device__ __forceinline__ void mma16816f16(float* d, const uint32_t* a,
                                            uint32_t b0, uint32_t b1) {
    asm volatile("mma.sync.aligned.m16n8k16.row.col.f32.f16.f16.f32 "
                 "{%0,%1,%2,%3}, {%4,%5,%6,%7}, {%8,%9}, {%0,%1,%2,%3};"
                 : "+f"(d[0]), "+f"(d[1]), "+f"(d[2]), "+f"(d[3])
                 : "r"(a[0]), "r"(a[1]), "r"(a[2]), "r"(a[3]), "r"(b0), "r"(b1));
}

// ---------------- batched winograd GEMM v6: 4 tiles/CTA, 3-stage pipeline -----
// CTA: 256k x (4 x 128t), one pos. 256 thr, 8 warps (4 wk x 2 wt), warp 64k x 64t.
// 16 chunk-iters per CTA: subtile = ci>>2, cc = (ci&3)*64. Epilogue at ci%4==3.
#define GROWS   384
#define GPITCH  144
#define GSTAGE  (GROWS * GPITCH)    // 55296
#define NGSTAGE 3
#define GSMEM   (NGSTAGE * GSTAGE)  // 165888
#define KCHUNK  64
#define NCI     16                  // 4 subtiles x 4 chunks

__device__ __forceinline__ void gemm_stage(char* base,
                                           const __half* __restrict__ gt,
                                           const __half* __restrict__ dt,
                                           int pos, int tbase, int ci, int t) {
    const int t0 = (tbase + (ci >> 2)) * 128;
    const int cc = (ci & 3) * KCHUNK;
#pragma unroll
    for (int i = 0; i < 12; ++i) {
        int u    = t + 256 * i;               // 0..3071
        int row  = u >> 3;                    // 0..383
        int seg  = u & 7;                     // 16B segment within 128B row
        const void* src;
        if (row < 256)
            src = gt + ((size_t)pos * K_OUT + row) * C_IN + cc + seg * 8;
        else
            src = dt + (size_t)pos * DT_POS_STRIDE
                     + (size_t)(t0 + row - 256) * C_IN + cc + seg * 8;
        cp_async16(base + row * GPITCH + seg * 16, src, true);
    }
}

__global__ void __launch_bounds__(256, 1)
wino_gemm(const __half* __restrict__ gt, const __half* __restrict__ dt,
          __half* __restrict__ mt) {
    extern __shared__ char smem[];
    const int tbase = blockIdx.x * 4;          // 4 subtiles of 128 tiles
    const int pos   = blockIdx.y;              // 0..15

    const int t    = threadIdx.x;
    const int lane = t & 31;
    const int warp = t >> 5;
    const int wk   = warp & 3;                 // 64-k group
    const int wt   = warp >> 2;                // 64-t group

    float acc[4][8][4];
#pragma unroll
    for (int i = 0; i < 4; ++i)
#pragma unroll
        for (int j = 0; j < 8; ++j)
#pragma unroll
            for (int v = 0; v < 4; ++v) acc[i][j][v] = 0.0f;

    // prologue: stages 0,1
    gemm_stage(smem + 0 * GSTAGE, gt, dt, pos, tbase, 0, t);
    cp_commit();
    gemm_stage(smem + 1 * GSTAGE, gt, dt, pos, tbase, 1, t);
    cp_commit();

    const uint32_t su = (uint32_t)__cvta_generic_to_shared(smem);
    const int a_off = (lane & 15) * GPITCH + (lane >> 4) * 16;
    const int b_off = ((lane & 7) + (lane >> 4) * 8) * GPITCH + ((lane >> 3) & 1) * 16;

    const int g  = lane >> 2;
    const int tc = lane & 3;
    __half* mbase = mt + (size_t)pos * MT_POS_STRIDE;

    int cur = 0, nxt2 = 2;
#pragma unroll 1
    for (int ci = 0; ci < NCI; ++ci) {
        __syncthreads();   // all warps done reading the buffer stage ci+2 reuses

        if (ci + 2 < NCI) {
            gemm_stage(smem + nxt2 * GSTAGE, gt, dt, pos, tbase, ci + 2, t);
            cp_commit();
            cp_wait<2>();                      // stage ci complete
        } else if (ci + 1 < NCI) {
            cp_wait<1>();
        } else {
            cp_wait<0>();
        }
        __syncthreads();   // stage ci visible to all warps

        const uint32_t sA = su + cur * GSTAGE;
        const uint32_t sB = sA + 256 * GPITCH;

#pragma unroll
        for (int sc = 0; sc < 4; ++sc) {
            const int cb = sc * 32;            // 16-channel sub-block byte offset
            uint32_t a[4][4];
#pragma unroll
            for (int i = 0; i < 4; ++i)
                ldsm_x4(sA + (wk * 64 + i * 16) * GPITCH + cb + a_off,
                        a[i][0], a[i][1], a[i][2], a[i][3]);
#pragma unroll
            for (int j = 0; j < 4; ++j) {
                uint32_t b[4];
                ldsm_x4(sB + (wt * 64 + j * 16) * GPITCH + cb + b_off,
                        b[0], b[1], b[2], b[3]);
#pragma unroll
                for (int i = 0; i < 4; ++i) {
                    mma16816f16(acc[i][2 * j],     a[i], b[0], b[1]);
                    mma16816f16(acc[i][2 * j + 1], a[i], b[2], b[3]);
                }
            }
        }

        // subtile boundary: store + reset accumulators
        if ((ci & 3) == 3) {
            const int t0 = (tbase + (ci >> 2)) * 128;
#pragma unroll
            for (int i = 0; i < 4; ++i) {
                const int krow = wk * 64 + i * 16 + g;
#pragma unroll
                for (int j = 0; j < 8; ++j) {
                    const int tcol = t0 + wt * 64 + j * 8 + 2 * tc;
                    __half2 v0 = __floats2half2_rn(acc[i][j][0], acc[i][j][1]);
                    __half2 v1 = __floats2half2_rn(acc[i][j][2], acc[i][j][3]);
                    *reinterpret_cast<__half2*>(
                        &mbase[(size_t)krow * NTILES_ALL + tcol]) = v0;
                    *reinterpret_cast<__half2*>(
                        &mbase[(size_t)(krow + 8) * NTILES_ALL + tcol]) = v1;
                    acc[i][j][0] = 0.0f; acc[i][j][1] = 0.0f;
                    acc[i][j][2] = 0.0f; acc[i][j][3] = 0.0f;
                }
            }
        }

        cur  = (cur + 1 == NGSTAGE) ? 0 : cur + 1;
        nxt2 = (nxt2 + 1 == NGSTAGE) ? 0 : nxt2 + 1;
    }
}

// ---------------- inverse transform v2: 2 gtiles/thread, vectorized ----------
__global__ void __launch_bounds__(256)
wino_inverse(const __half* __restrict__ mt, float* __restrict__ out) {
    const size_t idx = (size_t)blockIdx.x * 256 + threadIdx.x;   // 4.2M
    const int gp = (int)(idx & (NTILES_ALL / 2 - 1));            // gtile pair
    const int k  = (int)(idx >> 14);
    const int gtile0 = gp * 2;

    float m0[16], m1[16];
#pragma unroll
    for (int p = 0; p < 16; ++p) {
        __half2 hv = *reinterpret_cast<const __half2*>(
            &mt[(size_t)p * MT_POS_STRIDE + (size_t)k * NTILES_ALL + gtile0]);
        float2 fv = __half22float2(hv);
        m0[p] = fv.x;
        m1[p] = fv.y;
    }

    float z0a[4], z1a[4], z0b[4], z1b[4];
#pragma unroll
    for (int i = 0; i < 4; ++i) {
        z0a[i] = m0[i * 4 + 0] + m0[i * 4 + 1] + m0[i * 4 + 2];
        z1a[i] = m0[i * 4 + 1] - m0[i * 4 + 2] - m0[i * 4 + 3];
        z0b[i] = m1[i * 4 + 0] + m1[i * 4 + 1] + m1[i * 4 + 2];
        z1b[i] = m1[i * 4 + 1] - m1[i * 4 + 2] - m1[i * 4 + 3];
    }
    float4 r0 = make_float4(z0a[0] + z0a[1] + z0a[2],
                            z1a[0] + z1a[1] + z1a[2],
                            z0b[0] + z0b[1] + z0b[2],
                            z1b[0] + z1b[1] + z1b[2]);
    float4 r1 = make_float4(z0a[1] - z0a[2] - z0a[3],
                            z1a[1] - z1a[2] - z1a[3],
                            z0b[1] - z0b[2] - z0b[3],
                            z1b[1] - z1b[2] - z1b[3]);

    const int n  = gtile0 >> 10;
    const int th = (gtile0 >> 5) & 31;
    const int tw = gtile0 & 31;              // even
    size_t ob = (((size_t)n * K_OUT + k) * HW + 2 * th) * HW + 2 * tw;
    *reinterpret_cast<float4*>(out + ob)      = r0;
    *reinterpret_cast<float4*>(out + ob + HW) = r1;
}

// ---------------- launch ----------------
extern "C" void kernel_launch(void* const* d_in, const int* in_sizes, int n_in,
                              void* d_out, int out_size) {
    const float* x = (const float*)d_in[0];
    const float* w = (const float*)d_in[1];
    if (in_sizes[0] != X_ELEMS) {
        x = (const float*)d_in[1];
        w = (const float*)d_in[0];
    }

    void *xq_p, *wq_p, *gt_p, *dt_p, *mt_p;
    cudaGetSymbolAddress(&xq_p, g_xq);
    cudaGetSymbolAddress(&wq_p, g_wq2);
    cudaGetSymbolAddress(&gt_p, g_gt);
    cudaGetSymbolAddress(&dt_p, g_dt);
    cudaGetSymbolAddress(&mt_p, g_mt);
    uint8_t* xq  = (uint8_t*)xq_p;
    uint8_t* wq2 = (uint8_t*)wq_p;
    __half*  gt  = (__half*)gt_p;
    __half*  dt  = (__half*)dt_p;
    __half*  mt  = (__half*)mt_p;

    cudaFuncSetAttribute(dt_transform,
                         cudaFuncAttributeMaxDynamicSharedMemorySize, 65536);
    cudaFuncSetAttribute(wino_gemm,
                         cudaFuncAttributeMaxDynamicSharedMemorySize, GSMEM);

    quant_x_nhwc<<<dim3(N_IMG, HW), 256>>>(x, xq);
    quant_w_repack<<<(NWBLK + 255) / 256, 256>>>(w, wq2);
    wg_transform<<<K_OUT, C_IN>>>(wq2, gt);
    dt_transform<<<dim3(N_IMG, NTILE), 256, 65536>>>(xq, dt);
    wino_gemm<<<dim3(64, 16), 256, GSMEM>>>(gt, dt, mt);
    wino_inverse<<<K_OUT * NTILES_ALL / 2 / 256, 256>>>(mt, (float*)d_out);
}

// round 16
// speedup vs baseline: 1.3799x; 1.0254x over previous
#include <cuda_runtime.h>
#include <cuda_fp16.h>
#include <cstdint>

// ---------------- problem constants ----------------
#define N_IMG   32
#define C_IN    256
#define HW      64
#define K_OUT   256
#define X_ELEMS (N_IMG * C_IN * HW * HW)          // 33554432
#define W_ELEMS (K_OUT * C_IN * 9)                // 589824
#define NWBLK   (W_ELEMS / 16)                    // 36864
#define NTILE   32
#define TILES_PER_IMG (NTILE * NTILE)             // 1024
#define NTILES_ALL (N_IMG * TILES_PER_IMG)        // 32768
#define DT_POS_STRIDE ((size_t)NTILES_ALL * C_IN) // 8388608
#define MT_POS_STRIDE ((size_t)K_OUT * NTILES_ALL)// 8388608

// ---------------- scratch ----------------
__device__ uint8_t g_xq[X_ELEMS];                     // NHWC fp8 (exact quantized)
__device__ uint8_t g_wq2[9 * K_OUT * C_IN];           // [rs][k][c] fp8 (exact)
__device__ __half  g_gt[16 * K_OUT * C_IN];           // winograd weights fp16
__device__ __half  g_dt[16ull * DT_POS_STRIDE];       // winograd data fp16
__device__ __half  g_mt[16ull * MT_POS_STRIDE];       // winograd product fp16

// ---------------- fp8 helpers ----------------
__device__ __forceinline__ uint16_t pack_e4m3_x2(float lo, float hi) {
    uint16_t r;
    asm volatile("cvt.rn.satfinite.e4m3x2.f32 %0, %1, %2;" : "=h"(r) : "f"(hi), "f"(lo));
    return r;
}
__device__ __forceinline__ uint8_t f32_to_e4m3(float v) {
    uint16_t r;
    asm volatile("cvt.rn.satfinite.e4m3x2.f32 %0, %1, %2;" : "=h"(r) : "f"(0.0f), "f"(v));
    return (uint8_t)(r & 0xFF);
}
__device__ __forceinline__ float e4m3_to_f32(uint8_t b) {
    uint16_t s = b;
    uint32_t h2;
    asm("cvt.rn.f16x2.e4m3x2 %0, %1;" : "=r"(h2) : "h"(s));
    __half lo = __ushort_as_half((uint16_t)(h2 & 0xFFFF));
    return __half2float(lo);
}

// ---------------- fake-quant core (exact pow2 scale + RTN E2M1, ties-up) ------
__device__ __forceinline__ void quant16f(const float* __restrict__ v,
                                         float* __restrict__ q) {
    float amax = 0.0f;
#pragma unroll
    for (int i = 0; i < 16; ++i) amax = fmaxf(amax, fabsf(v[i]));
    float scale = 1.0f;
    if (amax > 0.0f) {
        float y = fmaxf(amax, 1e-30f) / 6.0f;
        int e;
        float m = frexpf(y, &e);
        scale = ldexpf(1.0f, (m == 0.5f) ? (e - 1) : e);
    }
    float inv = 1.0f / scale;
#pragma unroll
    for (int i = 0; i < 16; ++i) {
        float u = v[i] * inv;                 // exact (pow2)
        float a = fabsf(u);
        float g;
        if (a < 1.75f)      g = floorf(2.0f * a + 0.5f) * 0.5f;  // 0,.5,1,1.5 ties-up
        else if (a < 3.5f)  g = floorf(a + 0.5f);                // 2,3 ties-up
        else                g = (a < 5.0f) ? 4.0f : 6.0f;        // 4,6
        q[i] = copysignf(g, u) * scale;       // exact in e4m3
    }
}

// ---------------- x quant -> NHWC fp8 ----------------
__global__ void __launch_bounds__(256)
quant_x_nhwc(const float* __restrict__ x, uint8_t* __restrict__ xq) {
    __shared__ uint16_t buf[64][136];
    const int n = blockIdx.x;
    const int h = blockIdx.y;
    const int t = threadIdx.x;
    const int cp  = t & 127;
    const int wb0 = t >> 7;

#pragma unroll
    for (int wbi = 0; wbi < 2; ++wbi) {
        int wb = wb0 + wbi * 2;
        const float* base = x + (((size_t)n * C_IN + 2 * cp) * HW + h) * HW + wb * 16;
        const float4* p0 = reinterpret_cast<const float4*>(base);
        const float4* p1 = reinterpret_cast<const float4*>(base + (size_t)HW * HW);
        float v0[16], v1[16];
#pragma unroll
        for (int i = 0; i < 4; ++i) {
            float4 a = p0[i];
            v0[i * 4 + 0] = a.x; v0[i * 4 + 1] = a.y; v0[i * 4 + 2] = a.z; v0[i * 4 + 3] = a.w;
            float4 b = p1[i];
            v1[i * 4 + 0] = b.x; v1[i * 4 + 1] = b.y; v1[i * 4 + 2] = b.z; v1[i * 4 + 3] = b.w;
        }
        float q0[16], q1[16];
        quant16f(v0, q0);
        quant16f(v1, q1);
#pragma unroll
        for (int j = 0; j < 16; ++j)
            buf[wb * 16 + j][cp] = pack_e4m3_x2(q0[j], q1[j]);
    }
    __syncthreads();

    uint8_t* orow = xq + (((size_t)n * HW + h) * HW) * C_IN;
#pragma unroll
    for (int i = 0; i < 4; ++i) {
        int idx = t + 256 * i;
        int p   = idx >> 4;
        int qd  = idx & 15;
        uint4 val = *reinterpret_cast<const uint4*>(&buf[p][qd * 8]);
        *reinterpret_cast<uint4*>(orow + (size_t)p * C_IN + qd * 16) = val;
    }
}

// ---------------- w quant + repack -> [rs][k][c] fp8 ----------------
__global__ void quant_w_repack(const float* __restrict__ w,
                               uint8_t* __restrict__ wq2) {
    int b = blockIdx.x * blockDim.x + threadIdx.x;
    if (b >= NWBLK) return;
    const float4* src = reinterpret_cast<const float4*>(w) + (size_t)b * 4;
    float4 t0 = src[0], t1 = src[1], t2 = src[2], t3 = src[3];
    float v[16] = {t0.x, t0.y, t0.z, t0.w, t1.x, t1.y, t1.z, t1.w,
                   t2.x, t2.y, t2.z, t2.w, t3.x, t3.y, t3.z, t3.w};
    float q[16];
    quant16f(v, q);
#pragma unroll
    for (int i = 0; i < 16; ++i) {
        int f  = b * 16 + i;
        int k  = f / 2304;
        int r2 = f - k * 2304;
        int c  = r2 / 9;
        int rs = r2 - c * 9;
        wq2[((size_t)rs * K_OUT + k) * C_IN + c] = f32_to_e4m3(q[i]);
    }
}

// ---------------- winograd weight transform (proven) ----------------
__global__ void __launch_bounds__(256)
wg_transform(const uint8_t* __restrict__ wq2, __half* __restrict__ gt) {
    int k = blockIdx.x;
    int c = threadIdx.x;
    float w9[9];
#pragma unroll
    for (int rs = 0; rs < 9; ++rs)
        w9[rs] = e4m3_to_f32(wq2[((size_t)rs * K_OUT + k) * C_IN + c]);
    float a[4][3];
#pragma unroll
    for (int j = 0; j < 3; ++j) {
        float w0 = w9[0 * 3 + j], w1 = w9[1 * 3 + j], w2 = w9[2 * 3 + j];
        a[0][j] = w0;
        a[1][j] = 0.5f * (w0 + w1 + w2);
        a[2][j] = 0.5f * (w0 - w1 + w2);
        a[3][j] = w2;
    }
#pragma unroll
    for (int i = 0; i < 4; ++i) {
        float u0 = a[i][0], u1 = a[i][1], u2 = a[i][2];
        float u[4] = {u0, 0.5f * (u0 + u1 + u2), 0.5f * (u0 - u1 + u2), u2};
#pragma unroll
        for (int j = 0; j < 4; ++j)
            gt[((size_t)(i * 4 + j) * K_OUT + k) * C_IN + c] = __float2half(u[j]);
    }
}

// ---------------- cp.async helpers ----------------
__device__ __forceinline__ void cp_async16(void* dst, const void* src, bool pred) {
    uint32_t d = (uint32_t)__cvta_generic_to_shared(dst);
    int sz = pred ? 16 : 0;
    asm volatile("cp.async.cg.shared.global [%0], [%1], 16, %2;\n"
                 :: "r"(d), "l"(src), "r"(sz));
}
__device__ __forceinline__ void cp_commit() {
    asm volatile("cp.async.commit_group;\n");
}
template <int N>
__device__ __forceinline__ void cp_wait() {
    asm volatile("cp.async.wait_group %0;\n" :: "n"(N));
}

// ---------------- winograd data transform (proven, 46us) ----------------
__global__ void __launch_bounds__(256)
dt_transform(const uint8_t* __restrict__ xq, __half* __restrict__ dt) {
    extern __shared__ uint8_t sx[];
    const int n  = blockIdx.x;
    const int th = blockIdx.y;
    const int t  = threadIdx.x;

#pragma unroll
    for (int i = 0; i < 16; ++i) {
        int idx = t + 256 * i;
        int h1  = idx >> 10;
        int rem = idx & 1023;
        int w   = rem >> 4;
        int cq  = rem & 15;
        int gh  = th * 2 - 1 + h1;
        bool ok = (unsigned)gh < (unsigned)HW;
        cp_async16(sx + ((size_t)h1 * 64 + w) * 256 + cq * 16,
                   xq + (((size_t)n * HW + (ok ? gh : 0)) * HW + w) * C_IN + cq * 16, ok);
    }
    cp_commit();
    cp_wait<0>();
    __syncthreads();

    const int cp  = t & 127;
    const int twh = t >> 7;
    const __half2 zero = __floats2half2_rn(0.f, 0.f);

#pragma unroll 1
    for (int j = 0; j < 16; ++j) {
        int tw = j * 2 + twh;
        __half2 d[4][4];
#pragma unroll
        for (int wi = 0; wi < 4; ++wi) {
            int w = 2 * tw - 1 + wi;
            bool ok = (unsigned)w < (unsigned)HW;
#pragma unroll
            for (int h1 = 0; h1 < 4; ++h1) {
                if (ok) {
                    uint16_t u = *reinterpret_cast<const uint16_t*>(
                        sx + ((size_t)h1 * 64 + w) * 256 + 2 * cp);
                    uint32_t h2;
                    asm("cvt.rn.f16x2.e4m3x2 %0, %1;" : "=r"(h2) : "h"(u));
                    d[h1][wi] = *reinterpret_cast<__half2*>(&h2);
                } else {
                    d[h1][wi] = zero;
                }
            }
        }
        __half2 e[4][4];
#pragma unroll
        for (int h1 = 0; h1 < 4; ++h1) {
            e[h1][0] = __hsub2(d[h1][0], d[h1][2]);
            e[h1][1] = __hadd2(d[h1][1], d[h1][2]);
            e[h1][2] = __hsub2(d[h1][2], d[h1][1]);
            e[h1][3] = __hsub2(d[h1][1], d[h1][3]);
        }
        size_t tb = ((size_t)n * TILES_PER_IMG + th * NTILE + tw) * C_IN + 2 * cp;
#pragma unroll
        for (int jj = 0; jj < 4; ++jj) {
            __half2 D[4];
            D[0] = __hsub2(e[0][jj], e[2][jj]);
            D[1] = __hadd2(e[1][jj], e[2][jj]);
            D[2] = __hsub2(e[2][jj], e[1][jj]);
            D[3] = __hsub2(e[1][jj], e[3][jj]);
#pragma unroll
            for (int ii = 0; ii < 4; ++ii)
                *reinterpret_cast<uint32_t*>(&dt[(size_t)(ii * 4 + jj) * DT_POS_STRIDE + tb]) =
                    *reinterpret_cast<uint32_t*>(&D[ii]);
        }
    }
}

// ---------------- ldsm / mma ----------------
__device__ __forceinline__ void ldsm_x4(uint32_t addr, uint32_t& r0, uint32_t& r1,
                                        uint32_t& r2, uint32_t& r3) {
    asm volatile("ldmatrix.sync.aligned.m8n8.x4.shared.b16 {%0,%1,%2,%3}, [%4];"
                 : "=r"(r0), "=r"(r1), "=r"(r2), "=r"(r3) : "r"(addr));
}
__device__ __forceinline__ void mma16816f16(float* d, const uint32_t* a,
                                            uint32_t b0, uint32_t b1) {
    asm volatile("mma.sync.aligned.m16n8k16.row.col.f32.f16.f16.f32 "
                 "{%0,%1,%2,%3}, {%4,%5,%6,%7}, {%8,%9}, {%0,%1,%2,%3};"
                 : "+f"(d[0]), "+f"(d[1]), "+f"(d[2]), "+f"(d[3])
                 : "r"(a[0]), "r"(a[1]), "r"(a[2]), "r"(a[3]), "r"(b0), "r"(b1));
}

// ---------------- batched winograd GEMM v7: reg-double-buffered fragments -----
// CTA: 256k x (4 x 128t), one pos. 256 thr, 8 warps (4 wk x 2 wt), warp 64k x 64t.
// 16 chunk-iters per CTA: subtile = ci>>2, cc = (ci&3)*64. Epilogue at ci%4==3.
// Inner loop: ldsm for sub-chunk sc+1 overlaps the 32 MMAs of sub-chunk sc.
#define GROWS   384
#define GPITCH  144
#define GSTAGE  (GROWS * GPITCH)    // 55296
#define NGSTAGE 3
#define GSMEM   (NGSTAGE * GSTAGE)  // 165888
#define KCHUNK  64
#define NCI     16                  // 4 subtiles x 4 chunks

__device__ __forceinline__ void gemm_stage(char* base,
                                           const __half* __restrict__ gt,
                                           const __half* __restrict__ dt,
                                           int pos, int tbase, int ci, int t) {
    const int t0 = (tbase + (ci >> 2)) * 128;
    const int cc = (ci & 3) * KCHUNK;
#pragma unroll
    for (int i = 0; i < 12; ++i) {
        int u    = t + 256 * i;               // 0..3071
        int row  = u >> 3;                    // 0..383
        int seg  = u & 7;                     // 16B segment within 128B row
        const void* src;
        if (row < 256)
            src = gt + ((size_t)pos * K_OUT + row) * C_IN + cc + seg * 8;
        else
            src = dt + (size_t)pos * DT_POS_STRIDE
                     + (size_t)(t0 + row - 256) * C_IN + cc + seg * 8;
        cp_async16(base + row * GPITCH + seg * 16, src, true);
    }
}

__global__ void __launch_bounds__(256, 1)
wino_gemm(const __half* __restrict__ gt, const __half* __restrict__ dt,
          __half* __restrict__ mt) {
    extern __shared__ char smem[];
    const int tbase = blockIdx.x * 4;          // 4 subtiles of 128 tiles
    const int pos   = blockIdx.y;              // 0..15

    const int t    = threadIdx.x;
    const int lane = t & 31;
    const int warp = t >> 5;
    const int wk   = warp & 3;                 // 64-k group
    const int wt   = warp >> 2;                // 64-t group

    float acc[4][8][4];
#pragma unroll
    for (int i = 0; i < 4; ++i)
#pragma unroll
        for (int j = 0; j < 8; ++j)
#pragma unroll
            for (int v = 0; v < 4; ++v) acc[i][j][v] = 0.0f;

    // prologue: stages 0,1
    gemm_stage(smem + 0 * GSTAGE, gt, dt, pos, tbase, 0, t);
    cp_commit();
    gemm_stage(smem + 1 * GSTAGE, gt, dt, pos, tbase, 1, t);
    cp_commit();

    const uint32_t su = (uint32_t)__cvta_generic_to_shared(smem);
    const int a_off = (lane & 15) * GPITCH + (lane >> 4) * 16;
    const int b_off = ((lane & 7) + (lane >> 4) * 8) * GPITCH + ((lane >> 3) & 1) * 16;

    const int g  = lane >> 2;
    const int tc = lane & 3;
    __half* mbase = mt + (size_t)pos * MT_POS_STRIDE;

    // register-double-buffered fragments
    uint32_t af[2][4][4], bf[2][4][4];

    int cur = 0, nxt2 = 2;
#pragma unroll 1
    for (int ci = 0; ci < NCI; ++ci) {
        __syncthreads();   // all warps done reading the buffer stage ci+2 reuses

        if (ci + 2 < NCI) {
            gemm_stage(smem + nxt2 * GSTAGE, gt, dt, pos, tbase, ci + 2, t);
            cp_commit();
            cp_wait<2>();                      // stage ci complete
        } else if (ci + 1 < NCI) {
            cp_wait<1>();
        } else {
            cp_wait<0>();
        }
        __syncthreads();   // stage ci visible to all warps

        const uint32_t sA = su + cur * GSTAGE;
        const uint32_t sB = sA + 256 * GPITCH;

        // load fragments for sub-chunk 0
#pragma unroll
        for (int i = 0; i < 4; ++i)
            ldsm_x4(sA + (wk * 64 + i * 16) * GPITCH + 0 + a_off,
                    af[0][i][0], af[0][i][1], af[0][i][2], af[0][i][3]);
#pragma unroll
        for (int j = 0; j < 4; ++j)
            ldsm_x4(sB + (wt * 64 + j * 16) * GPITCH + 0 + b_off,
                    bf[0][j][0], bf[0][j][1], bf[0][j][2], bf[0][j][3]);

#pragma unroll
        for (int sc = 0; sc < 4; ++sc) {
            const int cb  = sc & 1;
            // prefetch sub-chunk sc+1 fragments (independent regs -> overlaps MMA)
            if (sc < 3) {
                const int ncb = cb ^ 1;
                const int off = (sc + 1) * 32;
#pragma unroll
                for (int i = 0; i < 4; ++i)
                    ldsm_x4(sA + (wk * 64 + i * 16) * GPITCH + off + a_off,
                            af[ncb][i][0], af[ncb][i][1], af[ncb][i][2], af[ncb][i][3]);
#pragma unroll
                for (int j = 0; j < 4; ++j)
                    ldsm_x4(sB + (wt * 64 + j * 16) * GPITCH + off + b_off,
                            bf[ncb][j][0], bf[ncb][j][1], bf[ncb][j][2], bf[ncb][j][3]);
            }
#pragma unroll
            for (int j = 0; j < 4; ++j) {
#pragma unroll
                for (int i = 0; i < 4; ++i) {
                    mma16816f16(acc[i][2 * j],     af[cb][i], bf[cb][j][0], bf[cb][j][1]);
                    mma16816f16(acc[i][2 * j + 1], af[cb][i], bf[cb][j][2], bf[cb][j][3]);
                }
            }
        }

        // subtile boundary: store + reset accumulators
        if ((ci & 3) == 3) {
            const int t0 = (tbase + (ci >> 2)) * 128;
#pragma unroll
            for (int i = 0; i < 4; ++i) {
                const int krow = wk * 64 + i * 16 + g;
#pragma unroll
                for (int j = 0; j < 8; ++j) {
                    const int tcol = t0 + wt * 64 + j * 8 + 2 * tc;
                    __half2 v0 = __floats2half2_rn(acc[i][j][0], acc[i][j][1]);
                    __half2 v1 = __floats2half2_rn(acc[i][j][2], acc[i][j][3]);
                    *reinterpret_cast<__half2*>(
                        &mbase[(size_t)krow * NTILES_ALL + tcol]) = v0;
                    *reinterpret_cast<__half2*>(
                        &mbase[(size_t)(krow + 8) * NTILES_ALL + tcol]) = v1;
                    acc[i][j][0] = 0.0f; acc[i][j][1] = 0.0f;
                    acc[i][j][2] = 0.0f; acc[i][j][3] = 0.0f;
                }
            }
        }

        cur  = (cur + 1 == NGSTAGE) ? 0 : cur + 1;
        nxt2 = (nxt2 + 1 == NGSTAGE) ? 0 : nxt2 + 1;
    }
}

// ---------------- inverse transform v2: 2 gtiles/thread, vectorized ----------
__global__ void __launch_bounds__(256)
wino_inverse(const __half* __restrict__ mt, float* __restrict__ out) {
    const size_t idx = (size_t)blockIdx.x * 256 + threadIdx.x;   // 4.2M
    const int gp = (int)(idx & (NTILES_ALL / 2 - 1));            // gtile pair
    const int k  = (int)(idx >> 14);
    const int gtile0 = gp * 2;

    float m0[16], m1[16];
#pragma unroll
    for (int p = 0; p < 16; ++p) {
        __half2 hv = *reinterpret_cast<const __half2*>(
            &mt[(size_t)p * MT_POS_STRIDE + (size_t)k * NTILES_ALL + gtile0]);
        float2 fv = __half22float2(hv);
        m0[p] = fv.x;
        m1[p] = fv.y;
    }

    float z0a[4], z1a[4], z0b[4], z1b[4];
#pragma unroll
    for (int i = 0; i < 4; ++i) {
        z0a[i] = m0[i * 4 + 0] + m0[i * 4 + 1] + m0[i * 4 + 2];
        z1a[i] = m0[i * 4 + 1] - m0[i * 4 + 2] - m0[i * 4 + 3];
        z0b[i] = m1[i * 4 + 0] + m1[i * 4 + 1] + m1[i * 4 + 2];
        z1b[i] = m1[i * 4 + 1] - m1[i * 4 + 2] - m1[i * 4 + 3];
    }
    float4 r0 = make_float4(z0a[0] + z0a[1] + z0a[2],
                            z1a[0] + z1a[1] + z1a[2],
                            z0b[0] + z0b[1] + z0b[2],
                            z1b[0] + z1b[1] + z1b[2]);
    float4 r1 = make_float4(z0a[1] - z0a[2] - z0a[3],
                            z1a[1] - z1a[2] - z1a[3],
                            z0b[1] - z0b[2] - z0b[3],
                            z1b[1] - z1b[2] - z1b[3]);

    const int n  = gtile0 >> 10;
    const int th = (gtile0 >> 5) & 31;
    const int tw = gtile0 & 31;              // even
    size_t ob = (((size_t)n * K_OUT + k) * HW + 2 * th) * HW + 2 * tw;
    *reinterpret_cast<float4*>(out + ob)      = r0;
    *reinterpret_cast<float4*>(out + ob + HW) = r1;
}

// ---------------- launch ----------------
extern "C" void kernel_launch(void* const* d_in, const int* in_sizes, int n_in,
                              void* d_out, int out_size) {
    const float* x = (const float*)d_in[0];
    const float* w = (const float*)d_in[1];
    if (in_sizes[0] != X_ELEMS) {
        x = (const float*)d_in[1];
        w = (const float*)d_in[0];
    }

    void *xq_p, *wq_p, *gt_p, *dt_p, *mt_p;
    cudaGetSymbolAddress(&xq_p, g_xq);
    cudaGetSymbolAddress(&wq_p, g_wq2);
    cudaGetSymbolAddress(&gt_p, g_gt);
    cudaGetSymbolAddress(&dt_p, g_dt);
    cudaGetSymbolAddress(&mt_p, g_mt);
    uint8_t* xq  = (uint8_t*)xq_p;
    uint8_t* wq2 = (uint8_t*)wq_p;
    __half*  gt  = (__half*)gt_p;
    __half*  dt  = (__half*)dt_p;
    __half*  mt  = (__half*)mt_p;

    cudaFuncSetAttribute(dt_transform,
                         cudaFuncAttributeMaxDynamicSharedMemorySize, 65536);
    cudaFuncSetAttribute(wino_gemm,
                         cudaFuncAttributeMaxDynamicSharedMemorySize, GSMEM);

    quant_x_nhwc<<<dim3(N_IMG, HW), 256>>>(x, xq);
    quant_w_repack<<<(NWBLK + 255) / 256, 256>>>(w, wq2);
    wg_transform<<<K_OUT, C_IN>>>(wq2, gt);
    dt_transform<<<dim3(N_IMG, NTILE), 256, 65536>>>(xq, dt);
    wino_gemm<<<dim3(64, 16), 256, GSMEM>>>(gt, dt, mt);
    wino_inverse<<<K_OUT * NTILES_ALL / 2 / 256, 256>>>(mt, (float*)d_out);
}